// round 14
// baseline (speedup 1.0000x reference)
#include <cuda_runtime.h>
#include <cuda_bf16.h>
#include <math.h>
#include <cstdint>

#define D_MODEL 1024
#define HEADS   16
#define DH      64
#define SEQ     1024
#define BATCH   8
#define MROWS   (BATCH*SEQ)   // 8192

typedef __nv_bfloat16 bf16;

// ---- scratch (no cudaMalloc allowed) ----
__device__ bf16 g_xh[MROWS*D_MODEL];
__device__ bf16 g_xl[MROWS*D_MODEL];
__device__ bf16 g_Qh[MROWS*D_MODEL];
__device__ bf16 g_Ql[MROWS*D_MODEL];
__device__ bf16 g_Kh[MROWS*D_MODEL];
__device__ bf16 g_Kl[MROWS*D_MODEL];
__device__ bf16 g_Vh[MROWS*D_MODEL];
__device__ bf16 g_Vl[MROWS*D_MODEL];
__device__ bf16 g_Oh[MROWS*D_MODEL];
__device__ bf16 g_Ol[MROWS*D_MODEL];
__device__ bf16 g_Wh[4][D_MODEL*D_MODEL];  // natural [k][n]
__device__ bf16 g_Wl[4][D_MODEL*D_MODEL];

#define QSC (0.125f * 1.44269504088896f)   // 1/sqrt(dh) * log2(e)

// ============================================================
// PTX helpers (sm_80-era only; tcgen05 unavailable at .target sm_103)
// ============================================================
__device__ __forceinline__ uint32_t smem_u32(const void* p) {
    uint32_t a;
    asm("{ .reg .u64 t; cvta.to.shared.u64 t, %1; cvt.u32.u64 %0, t; }"
        : "=r"(a) : "l"(p));
    return a;
}
__device__ __forceinline__ void cpa16(uint32_t dst, const void* src) {
    asm volatile("cp.async.cg.shared.global [%0], [%1], 16;"
                 :: "r"(dst), "l"(src) : "memory");
}
#define CP_COMMIT() asm volatile("cp.async.commit_group;" ::: "memory")
#define CP_WAIT1()  asm volatile("cp.async.wait_group 1;" ::: "memory")
#define CP_WAIT0()  asm volatile("cp.async.wait_group 0;" ::: "memory")

__device__ __forceinline__ void ldsm_x4(uint32_t* r, uint32_t addr) {
    asm volatile("ldmatrix.sync.aligned.m8n8.x4.shared.b16 {%0,%1,%2,%3}, [%4];"
                 : "=r"(r[0]), "=r"(r[1]), "=r"(r[2]), "=r"(r[3]) : "r"(addr));
}
__device__ __forceinline__ void ldsm_x4t(uint32_t* r, uint32_t addr) {
    asm volatile("ldmatrix.sync.aligned.m8n8.x4.trans.shared.b16 {%0,%1,%2,%3}, [%4];"
                 : "=r"(r[0]), "=r"(r[1]), "=r"(r[2]), "=r"(r[3]) : "r"(addr));
}
__device__ __forceinline__ void mma16816(float* c, const uint32_t* a,
                                         uint32_t b0, uint32_t b1) {
    asm volatile(
        "mma.sync.aligned.m16n8k16.row.col.f32.bf16.bf16.f32 "
        "{%0,%1,%2,%3}, {%4,%5,%6,%7}, {%8,%9}, {%0,%1,%2,%3};"
        : "+f"(c[0]), "+f"(c[1]), "+f"(c[2]), "+f"(c[3])
        : "r"(a[0]), "r"(a[1]), "r"(a[2]), "r"(a[3]), "r"(b0), "r"(b1));
}
__device__ __forceinline__ float ex2f(float x) {
    float r; asm("ex2.approx.f32 %0, %1;" : "=f"(r) : "f"(x)); return r;
}
__device__ __forceinline__ uint32_t pk2(float lo, float hi) {   // bf16x2 {lo,hi}
    uint32_t d;
    asm("cvt.rn.bf16x2.f32 %0, %1, %2;" : "=r"(d) : "f"(hi), "f"(lo));
    return d;
}
__device__ __forceinline__ float2 upk2(uint32_t v) {
    __nv_bfloat162 t = *reinterpret_cast<__nv_bfloat162*>(&v);
    return __bfloat1622float2(t);
}

// ============================================================
// splits: fp32 -> bf16 hi/lo
// ============================================================
__device__ __forceinline__ void split4(const float* __restrict__ X,
                                       bf16* __restrict__ Xh,
                                       bf16* __restrict__ Xl, size_t i) {
    float4 v = *(const float4*)&X[i];
    float a[4] = {v.x, v.y, v.z, v.w};
    bf16 h[4], l[4];
    #pragma unroll
    for (int j = 0; j < 4; j++) {
        h[j] = __float2bfloat16_rn(a[j]);
        l[j] = __float2bfloat16_rn(a[j] - __bfloat162float(h[j]));
    }
    *(__nv_bfloat162*)&Xh[i]     = __halves2bfloat162(h[0], h[1]);
    *(__nv_bfloat162*)&Xh[i + 2] = __halves2bfloat162(h[2], h[3]);
    *(__nv_bfloat162*)&Xl[i]     = __halves2bfloat162(l[0], l[1]);
    *(__nv_bfloat162*)&Xl[i + 2] = __halves2bfloat162(l[2], l[3]);
}
__global__ void fsplit(const float* __restrict__ X,
                       bf16* __restrict__ Xh, bf16* __restrict__ Xl) {
    size_t i = (size_t)(blockIdx.x * blockDim.x + threadIdx.x) * 4;
    split4(X, Xh, Xl, i);
}
__global__ void wsplit4(const float* __restrict__ w0, const float* __restrict__ w1,
                        const float* __restrict__ w2, const float* __restrict__ w3,
                        bf16* __restrict__ Wh, bf16* __restrict__ Wl) {
    int z = blockIdx.z;
    const float* W = (z == 0) ? w0 : (z == 1) ? w1 : (z == 2) ? w2 : w3;
    size_t off = (size_t)z * D_MODEL * D_MODEL;
    size_t i = (size_t)(blockIdx.x * blockDim.x + threadIdx.x) * 4;
    split4(W, Wh + off, Wl + off, i);
}

// ============================================================
// hgemm10 (FIXED): C[M,1024] = A @ W via bf16 3-split on mma.sync.
//   CTA 128x128, FOUR warps (2m x 2n) of 64x64, 128 threads.
//   Per k16: 16 ldsm feed 96 mma (6 mma/ldsm vs R12's 4) at the
//   SAME 2-CTAs/SM occupancy class (smem 113.6KB, regs ~200).
//   BK=32, 3-stage ring, fused term-outer passes.
//   R13 bug fixed: cg loop is 4 groups, warp n-offset is wn*128 B.
// ============================================================
#define AST9 80                         // A smem row stride (40 bf16)
#define BST  272                        // B smem row stride (136 bf16)
#define ABYT9 (128 * AST9)              // 10240
#define BBYT9 (32 * BST)                // 8704
#define STG9 (2 * ABYT9 + 2 * BBYT9)    // 37888
#define NST9 32                         // K chunks of 32
#define GEM_SMEM (3 * STG9)             // 113664  -> 2 CTAs/SM

__device__ __forceinline__ void gload10(uint32_t st,
    const bf16* __restrict__ Ah, const bf16* __restrict__ Al,
    const bf16* __restrict__ Bh, const bf16* __restrict__ Bl,
    int m0, int n0, int kk0, int tid)
{
    #pragma unroll
    for (int t = 0; t < 4; t++) {            // A: 128x32 hi+lo (512 chunks ea)
        int idx = tid + (t << 7);
        int r = idx >> 2, c = idx & 3;
        size_t go = (size_t)(m0 + r) * D_MODEL + kk0 + c * 8;
        uint32_t so = st + r * AST9 + c * 16;
        cpa16(so, Ah + go);
        cpa16(so + ABYT9, Al + go);
    }
    #pragma unroll
    for (int t = 0; t < 4; t++) {            // B: 32x128 hi+lo (512 chunks ea)
        int idx = tid + (t << 7);
        int r = idx >> 4, c = idx & 15;
        size_t go = (size_t)(kk0 + r) * D_MODEL + n0 + c * 8;
        uint32_t so = st + 2 * ABYT9 + r * BST + c * 16;
        cpa16(so, Bh + go);
        cpa16(so + BBYT9, Bl + go);
    }
}

// fused 3-term pass over one BK=32 chunk, term-outer, 64x64 warp tile
__device__ __forceinline__ void gpass10(float acc[32][4],
    uint32_t aH, uint32_t aL, uint32_t bH, uint32_t bL,
    int wm, int wn, int lr, int lc)
{
    #pragma unroll
    for (int k16 = 0; k16 < 2; k16++) {
        uint32_t ah[4][4], al[4][4];
        #pragma unroll
        for (int mt = 0; mt < 4; mt++) {
            uint32_t aoff = (wm * 64 + mt * 16 + lr) * AST9 + k16 * 32 + lc * 16;
            ldsm_x4(ah[mt], aH + aoff);
            ldsm_x4(al[mt], aL + aoff);
        }
        #pragma unroll
        for (int cg = 0; cg < 4; cg++) {    // FIX: 4 column groups
            uint32_t boff = (k16 * 16 + lr) * BST
                          + wn * 128 + cg * 32 + lc * 16;  // FIX: wn*128 bytes
            uint32_t bh4[4], bl4[4];
            ldsm_x4t(bh4, bH + boff);
            ldsm_x4t(bl4, bL + boff);
            // term 1: Ah*Bh
            #pragma unroll
            for (int half = 0; half < 2; half++)
                #pragma unroll
                for (int mt = 0; mt < 4; mt++)
                    mma16816(acc[mt * 8 + cg * 2 + half], ah[mt],
                             bh4[half * 2], bh4[half * 2 + 1]);
            // term 2: Ah*Bl
            #pragma unroll
            for (int half = 0; half < 2; half++)
                #pragma unroll
                for (int mt = 0; mt < 4; mt++)
                    mma16816(acc[mt * 8 + cg * 2 + half], ah[mt],
                             bl4[half * 2], bl4[half * 2 + 1]);
            // term 3: Al*Bh
            #pragma unroll
            for (int half = 0; half < 2; half++)
                #pragma unroll
                for (int mt = 0; mt < 4; mt++)
                    mma16816(acc[mt * 8 + cg * 2 + half], al[mt],
                             bh4[half * 2], bh4[half * 2 + 1]);
        }
    }
}

template<int MODE>
__global__ __launch_bounds__(128, 2) void hgemm10(
    const bf16* __restrict__ Ah, const bf16* __restrict__ Al,
    const bf16* __restrict__ BhB, const bf16* __restrict__ BlB,
    float* __restrict__ C,
    bf16* __restrict__ Ch0, bf16* __restrict__ Cl0,
    bf16* __restrict__ Ch1, bf16* __restrict__ Cl1,
    bf16* __restrict__ Ch2, bf16* __restrict__ Cl2)
{
    extern __shared__ char dsm[];
    const uint32_t sb = smem_u32(dsm);

    const int tid = threadIdx.x;
    const int wid = tid >> 5;               // 0..3
    const int lane = tid & 31;
    const int wm = wid >> 1, wn = wid & 1;  // 2m x 2n, 64x64 tiles
    const int lr = lane & 15, lc = lane >> 4;
    const int m0 = blockIdx.y << 7;
    const int n0 = blockIdx.x << 7;
    const int z  = blockIdx.z;

    const bf16* Bh = BhB + (size_t)z * D_MODEL * D_MODEL;
    const bf16* Bl = BlB + (size_t)z * D_MODEL * D_MODEL;

    float acc[32][4];
    #pragma unroll
    for (int i = 0; i < 32; i++)
        #pragma unroll
        for (int j = 0; j < 4; j++) acc[i][j] = 0.f;

    // prologue: 2 stages in flight
    gload10(sb,        Ah, Al, Bh, Bl, m0, n0, 0,  tid);
    CP_COMMIT();
    gload10(sb + STG9, Ah, Al, Bh, Bl, m0, n0, 32, tid);
    CP_COMMIT();

    #pragma unroll 1
    for (int s = 0; s < NST9; s++) {
        if (s < NST9 - 2) CP_WAIT1();
        else              CP_WAIT0();
        __syncthreads();
        if (s + 2 < NST9) {
            int slot = (s + 2) % 3;
            gload10(sb + slot * STG9, Ah, Al, Bh, Bl,
                    m0, n0, (s + 2) << 5, tid);
            CP_COMMIT();
        }
        const uint32_t base = sb + (s % 3) * STG9;
        gpass10(acc, base, base + ABYT9,
                base + 2 * ABYT9, base + 2 * ABYT9 + BBYT9,
                wm, wn, lr, lc);
    }

    const int g = lane >> 2, tg = lane & 3;
    const float scale = (MODE == 1 && z == 0) ? QSC : 1.0f;
    bf16* Ch = (z == 0) ? Ch0 : (z == 1) ? Ch1 : Ch2;
    bf16* Cl = (z == 0) ? Cl0 : (z == 1) ? Cl1 : Cl2;

    #pragma unroll
    for (int mt = 0; mt < 4; mt++) {
        int row = m0 + wm * 64 + mt * 16 + g;
        #pragma unroll
        for (int nt = 0; nt < 8; nt++) {
            int col = n0 + wn * 64 + nt * 8 + tg * 2;
            float* ac = acc[mt * 8 + nt];
            if (MODE == 0) {
                float* cp = &C[(size_t)row * D_MODEL + col];
                *(float2*)cp = make_float2(ac[0], ac[1]);
                *(float2*)(cp + 8 * D_MODEL) = make_float2(ac[2], ac[3]);
            } else {
                float v0 = ac[0] * scale, v1 = ac[1] * scale;
                float v2 = ac[2] * scale, v3 = ac[3] * scale;
                uint32_t h01 = pk2(v0, v1), h23 = pk2(v2, v3);
                float2 f01 = upk2(h01), f23 = upk2(h23);
                size_t o0 = (size_t)row * D_MODEL + col;
                size_t o1 = o0 + 8 * D_MODEL;
                *(uint32_t*)&Ch[o0] = h01;
                *(uint32_t*)&Ch[o1] = h23;
                *(uint32_t*)&Cl[o0] = pk2(v0 - f01.x, v1 - f01.y);
                *(uint32_t*)&Cl[o1] = pk2(v2 - f23.x, v3 - f23.y);
            }
        }
    }
}

// ============================================================
// attn_mma4 (R12, unchanged): flash attention, 128 queries/CTA,
// 4 warps x 32 q-rows, 2 CTAs/SM.
// ============================================================
#define AST 144
#define QTB4  (128 * AST)                // one 128x64 bf16 Q tile = 18432
#define KVB   (64 * AST)                 // one 64x64 bf16 tile = 9216
#define KVST  (4 * KVB)                  // Kh,Kl,Vh,Vl per stage = 36864
#define KVOFF4 (2 * QTB4)                // 36864
#define ATT_SMEM (KVOFF4 + 2 * KVST)     // 110592 -> 2 CTAs/SM

__device__ __forceinline__ void kvload4(uint32_t st,
    const bf16* __restrict__ Kh, const bf16* __restrict__ Kl,
    const bf16* __restrict__ Vh, const bf16* __restrict__ Vl,
    size_t gbase, int tid)
{
    #pragma unroll
    for (int t = 0; t < 4; t++) {
        int idx = tid + (t << 7);
        int r = idx >> 3, c = idx & 7;
        size_t go = gbase + (size_t)r * D_MODEL + c * 8;
        uint32_t so = st + r * AST + c * 16;
        cpa16(so,           Kh + go);
        cpa16(so + KVB,     Kl + go);
        cpa16(so + 2 * KVB, Vh + go);
        cpa16(so + 3 * KVB, Vl + go);
    }
}

__global__ __launch_bounds__(128, 2) void attn_mma4(
    const bf16* __restrict__ Qh, const bf16* __restrict__ Ql,
    const bf16* __restrict__ Kh, const bf16* __restrict__ Kl,
    const bf16* __restrict__ Vh, const bf16* __restrict__ Vl,
    bf16* __restrict__ Oh, bf16* __restrict__ Ol)
{
    extern __shared__ char dsm[];
    const uint32_t sb = smem_u32(dsm);

    const int tid = threadIdx.x;
    const int wid = tid >> 5;
    const int lane = tid & 31;
    const int lr = lane & 15, lc = lane >> 4;
    const int g = lane >> 2, tg = lane & 3;
    const int qb = blockIdx.x, h = blockIdx.y, b = blockIdx.z;
    const size_t qrow0 = (size_t)(b * SEQ + qb * 128);
    const size_t hcol = h * DH;

    #pragma unroll
    for (int t = 0; t < 8; t++) {
        int idx = tid + (t << 7);
        int r = idx >> 3, c = idx & 7;
        size_t go = (qrow0 + r) * D_MODEL + hcol + c * 8;
        uint32_t so = sb + r * AST + c * 16;
        cpa16(so, Qh + go);
        cpa16(so + QTB4, Ql + go);
    }
    CP_COMMIT();

    kvload4(sb + KVOFF4, Kh, Kl, Vh, Vl, (size_t)(b * SEQ) * D_MODEL + hcol, tid);
    CP_COMMIT();

    float acco[16][4];
    #pragma unroll
    for (int i = 0; i < 16; i++)
        #pragma unroll
        for (int j = 0; j < 4; j++) acco[i][j] = 0.f;
    float mrow[4] = {-1e30f, -1e30f, -1e30f, -1e30f};
    float lrow[4] = {0.f, 0.f, 0.f, 0.f};

    #pragma unroll 1
    for (int kb = 0; kb < 16; kb++) {
        if (kb < 15)
            kvload4(sb + KVOFF4 + ((kb + 1) & 1) * KVST, Kh, Kl, Vh, Vl,
                    (size_t)(b * SEQ + (kb + 1) * 64) * D_MODEL + hcol, tid);
        CP_COMMIT();
        CP_WAIT1();
        __syncthreads();

        const uint32_t kst = sb + KVOFF4 + (kb & 1) * KVST;
        const uint32_t khT = kst, klT = kst + KVB;
        const uint32_t vhT = kst + 2 * KVB, vlT = kst + 3 * KVB;

        float accs[16][4];
        #pragma unroll
        for (int i = 0; i < 16; i++)
            #pragma unroll
            for (int j = 0; j < 4; j++) accs[i][j] = 0.f;

        #pragma unroll
        for (int kt = 0; kt < 4; kt++) {
            uint32_t ah[2][4], al[2][4], kfh[4][4], kfl[4][4];
            #pragma unroll
            for (int mt = 0; mt < 2; mt++) {
                uint32_t qoff = (wid * 32 + mt * 16 + lr) * AST + kt * 32 + lc * 16;
                ldsm_x4(ah[mt], sb + qoff);
                ldsm_x4(al[mt], sb + QTB4 + qoff);
            }
            #pragma unroll
            for (int j = 0; j < 4; j++) {
                uint32_t koff = (j * 16 + lr) * AST + kt * 32 + lc * 16;
                ldsm_x4(kfh[j], khT + koff);
                ldsm_x4(kfl[j], klT + koff);
            }
            #pragma unroll
            for (int mt = 0; mt < 2; mt++)
                #pragma unroll
                for (int j = 0; j < 4; j++) {
                    mma16816(accs[mt * 8 + 2 * j],     ah[mt], kfh[j][0], kfh[j][2]);
                    mma16816(accs[mt * 8 + 2 * j + 1], ah[mt], kfh[j][1], kfh[j][3]);
                }
            #pragma unroll
            for (int mt = 0; mt < 2; mt++)
                #pragma unroll
                for (int j = 0; j < 4; j++) {
                    mma16816(accs[mt * 8 + 2 * j],     ah[mt], kfl[j][0], kfl[j][2]);
                    mma16816(accs[mt * 8 + 2 * j + 1], ah[mt], kfl[j][1], kfl[j][3]);
                }
            #pragma unroll
            for (int mt = 0; mt < 2; mt++)
                #pragma unroll
                for (int j = 0; j < 4; j++) {
                    mma16816(accs[mt * 8 + 2 * j],     al[mt], kfh[j][0], kfh[j][2]);
                    mma16816(accs[mt * 8 + 2 * j + 1], al[mt], kfh[j][1], kfh[j][3]);
                }
        }

        #pragma unroll
        for (int mt = 0; mt < 2; mt++) {
            float mx0 = -1e30f, mx1 = -1e30f;
            #pragma unroll
            for (int nt = 0; nt < 8; nt++) {
                mx0 = fmaxf(mx0, fmaxf(accs[mt * 8 + nt][0], accs[mt * 8 + nt][1]));
                mx1 = fmaxf(mx1, fmaxf(accs[mt * 8 + nt][2], accs[mt * 8 + nt][3]));
            }
            mx0 = fmaxf(mx0, __shfl_xor_sync(0xffffffffu, mx0, 1));
            mx0 = fmaxf(mx0, __shfl_xor_sync(0xffffffffu, mx0, 2));
            mx1 = fmaxf(mx1, __shfl_xor_sync(0xffffffffu, mx1, 1));
            mx1 = fmaxf(mx1, __shfl_xor_sync(0xffffffffu, mx1, 2));
            float mn0 = fmaxf(mrow[mt * 2],     mx0);
            float mn1 = fmaxf(mrow[mt * 2 + 1], mx1);
            float al0 = ex2f(mrow[mt * 2]     - mn0);
            float al1 = ex2f(mrow[mt * 2 + 1] - mn1);
            mrow[mt * 2] = mn0; mrow[mt * 2 + 1] = mn1;
            float s0 = 0.f, s1 = 0.f;
            #pragma unroll
            for (int nt = 0; nt < 8; nt++) {
                float* a = accs[mt * 8 + nt];
                a[0] = ex2f(a[0] - mn0);
                a[1] = ex2f(a[1] - mn0);
                a[2] = ex2f(a[2] - mn1);
                a[3] = ex2f(a[3] - mn1);
                s0 += a[0] + a[1];
                s1 += a[2] + a[3];
            }
            s0 += __shfl_xor_sync(0xffffffffu, s0, 1);
            s0 += __shfl_xor_sync(0xffffffffu, s0, 2);
            s1 += __shfl_xor_sync(0xffffffffu, s1, 1);
            s1 += __shfl_xor_sync(0xffffffffu, s1, 2);
            lrow[mt * 2]     = lrow[mt * 2]     * al0 + s0;
            lrow[mt * 2 + 1] = lrow[mt * 2 + 1] * al1 + s1;
            #pragma unroll
            for (int nt = 0; nt < 8; nt++) {
                acco[mt * 8 + nt][0] *= al0; acco[mt * 8 + nt][1] *= al0;
                acco[mt * 8 + nt][2] *= al1; acco[mt * 8 + nt][3] *= al1;
            }
        }

        #pragma unroll
        for (int kt = 0; kt < 4; kt++) {
            uint32_t vbh[4][4], vbl[4][4];
            #pragma unroll
            for (int cg = 0; cg < 4; cg++) {
                uint32_t voff = (kt * 16 + lr) * AST + cg * 32 + lc * 16;
                ldsm_x4t(vbh[cg], vhT + voff);
                ldsm_x4t(vbl[cg], vlT + voff);
            }
            uint32_t ph[2][4], pl[2][4];
            #pragma unroll
            for (int mt = 0; mt < 2; mt++) {
                float* s0 = accs[mt * 8 + 2 * kt];
                float* s1 = accs[mt * 8 + 2 * kt + 1];
                ph[mt][0] = pk2(s0[0], s0[1]);
                ph[mt][1] = pk2(s0[2], s0[3]);
                ph[mt][2] = pk2(s1[0], s1[1]);
                ph[mt][3] = pk2(s1[2], s1[3]);
                float2 f0 = upk2(ph[mt][0]), f1 = upk2(ph[mt][1]);
                float2 f2 = upk2(ph[mt][2]), f3 = upk2(ph[mt][3]);
                pl[mt][0] = pk2(s0[0] - f0.x, s0[1] - f0.y);
                pl[mt][1] = pk2(s0[2] - f1.x, s0[3] - f1.y);
                pl[mt][2] = pk2(s1[0] - f2.x, s1[1] - f2.y);
                pl[mt][3] = pk2(s1[2] - f3.x, s1[3] - f3.y);
            }
            #pragma unroll
            for (int mt = 0; mt < 2; mt++)
                #pragma unroll
                for (int nt = 0; nt < 8; nt++)
                    mma16816(acco[mt * 8 + nt], ph[mt],
                             vbh[nt >> 1][(nt & 1) * 2],
                             vbh[nt >> 1][(nt & 1) * 2 + 1]);
            #pragma unroll
            for (int mt = 0; mt < 2; mt++)
                #pragma unroll
                for (int nt = 0; nt < 8; nt++)
                    mma16816(acco[mt * 8 + nt], pl[mt],
                             vbh[nt >> 1][(nt & 1) * 2],
                             vbh[nt >> 1][(nt & 1) * 2 + 1]);
            #pragma unroll
            for (int mt = 0; mt < 2; mt++)
                #pragma unroll
                for (int nt = 0; nt < 8; nt++)
                    mma16816(acco[mt * 8 + nt], ph[mt],
                             vbl[nt >> 1][(nt & 1) * 2],
                             vbl[nt >> 1][(nt & 1) * 2 + 1]);
        }
        __syncthreads();
    }

    #pragma unroll
    for (int mt = 0; mt < 2; mt++) {
        float inv0 = 1.f / lrow[mt * 2];
        float inv1 = 1.f / lrow[mt * 2 + 1];
        size_t r0 = (qrow0 + wid * 32 + mt * 16 + g) * D_MODEL + hcol;
        size_t r1 = r0 + 8 * D_MODEL;
        #pragma unroll
        for (int nt = 0; nt < 8; nt++) {
            int col = nt * 8 + tg * 2;
            float v0 = acco[mt * 8 + nt][0] * inv0;
            float v1 = acco[mt * 8 + nt][1] * inv0;
            float v2 = acco[mt * 8 + nt][2] * inv1;
            float v3 = acco[mt * 8 + nt][3] * inv1;
            uint32_t h01 = pk2(v0, v1), h23 = pk2(v2, v3);
            float2 f01 = upk2(h01), f23 = upk2(h23);
            *(uint32_t*)&Oh[r0 + col] = h01;
            *(uint32_t*)&Oh[r1 + col] = h23;
            *(uint32_t*)&Ol[r0 + col] = pk2(v0 - f01.x, v1 - f01.y);
            *(uint32_t*)&Ol[r1 + col] = pk2(v2 - f23.x, v3 - f23.y);
        }
    }
}

// ============================================================
extern "C" void kernel_launch(void* const* d_in, const int* in_sizes, int n_in,
                              void* d_out, int out_size)
{
    const float* x = (const float*)d_in[0];
    float* out = (float*)d_out;

    bf16 *xh, *xl, *qh, *ql, *kh, *kl, *vh, *vl, *oh, *ol, *bh, *bl;
    cudaGetSymbolAddress((void**)&xh, g_xh);
    cudaGetSymbolAddress((void**)&xl, g_xl);
    cudaGetSymbolAddress((void**)&qh, g_Qh);
    cudaGetSymbolAddress((void**)&ql, g_Ql);
    cudaGetSymbolAddress((void**)&kh, g_Kh);
    cudaGetSymbolAddress((void**)&kl, g_Kl);
    cudaGetSymbolAddress((void**)&vh, g_Vh);
    cudaGetSymbolAddress((void**)&vl, g_Vl);
    cudaGetSymbolAddress((void**)&oh, g_Oh);
    cudaGetSymbolAddress((void**)&ol, g_Ol);
    cudaGetSymbolAddress((void**)&bh, g_Wh);
    cudaGetSymbolAddress((void**)&bl, g_Wl);
    const size_t WSTR = (size_t)D_MODEL * D_MODEL;

    static int cfg_done = 0;
    if (!cfg_done) {
        cudaFuncSetAttribute(hgemm10<0>,
            cudaFuncAttributeMaxDynamicSharedMemorySize, GEM_SMEM);
        cudaFuncSetAttribute(hgemm10<1>,
            cudaFuncAttributeMaxDynamicSharedMemorySize, GEM_SMEM);
        cudaFuncSetAttribute(attn_mma4,
            cudaFuncAttributeMaxDynamicSharedMemorySize, ATT_SMEM);
        cfg_done = 1;
    }

    // splits: x, then all 4 weights in one launch
    fsplit<<<MROWS * D_MODEL / 1024, 256>>>(x, xh, xl);
    wsplit4<<<dim3(D_MODEL * D_MODEL / 1024, 1, 4), 256>>>(
        (const float*)d_in[1], (const float*)d_in[2],
        (const float*)d_in[3], (const float*)d_in[4], bh, bl);

    // QKV projections fused into one launch (grid.z selects W / output)
    hgemm10<1><<<dim3(D_MODEL / 128, MROWS / 128, 3), 128, GEM_SMEM>>>(
        xh, xl, bh, bl, nullptr, qh, ql, kh, kl, vh, vl);

    attn_mma4<<<dim3(SEQ / 128, HEADS, BATCH), 128, ATT_SMEM>>>(
        qh, ql, kh, kl, vh, vl, oh, ol);

    // final projection (W index 3)
    hgemm10<0><<<dim3(D_MODEL / 128, MROWS / 128, 1), 128, GEM_SMEM>>>(
        oh, ol, bh + 3 * WSTR, bl + 3 * WSTR, out,
        nullptr, nullptr, nullptr, nullptr, nullptr, nullptr);
}

// round 15
// speedup vs baseline: 1.0209x; 1.0209x over previous
#include <cuda_runtime.h>
#include <cuda_bf16.h>
#include <math.h>
#include <cstdint>

#define D_MODEL 1024
#define HEADS   16
#define DH      64
#define SEQ     1024
#define BATCH   8
#define MROWS   (BATCH*SEQ)   // 8192

typedef __nv_bfloat16 bf16;

// ---- scratch (no cudaMalloc allowed) ----
__device__ bf16 g_xh[MROWS*D_MODEL];
__device__ bf16 g_xl[MROWS*D_MODEL];
__device__ bf16 g_Qh[MROWS*D_MODEL];
__device__ bf16 g_Ql[MROWS*D_MODEL];
__device__ bf16 g_Kh[MROWS*D_MODEL];
__device__ bf16 g_Kl[MROWS*D_MODEL];
__device__ bf16 g_Vh[MROWS*D_MODEL];
__device__ bf16 g_Vl[MROWS*D_MODEL];
__device__ bf16 g_Oh[MROWS*D_MODEL];
__device__ bf16 g_Ol[MROWS*D_MODEL];
__device__ bf16 g_Wh[4][D_MODEL*D_MODEL];  // natural [k][n]
__device__ bf16 g_Wl[4][D_MODEL*D_MODEL];

#define QSC (0.125f * 1.44269504088896f)   // 1/sqrt(dh) * log2(e)

// ============================================================
// PTX helpers (sm_80-era only; tcgen05 unavailable at .target sm_103)
// ============================================================
__device__ __forceinline__ uint32_t smem_u32(const void* p) {
    uint32_t a;
    asm("{ .reg .u64 t; cvta.to.shared.u64 t, %1; cvt.u32.u64 %0, t; }"
        : "=r"(a) : "l"(p));
    return a;
}
__device__ __forceinline__ void cpa16(uint32_t dst, const void* src) {
    asm volatile("cp.async.cg.shared.global [%0], [%1], 16;"
                 :: "r"(dst), "l"(src) : "memory");
}
#define CP_COMMIT() asm volatile("cp.async.commit_group;" ::: "memory")
#define CP_WAIT1()  asm volatile("cp.async.wait_group 1;" ::: "memory")
#define CP_WAIT0()  asm volatile("cp.async.wait_group 0;" ::: "memory")

__device__ __forceinline__ void ldsm_x4(uint32_t* r, uint32_t addr) {
    asm volatile("ldmatrix.sync.aligned.m8n8.x4.shared.b16 {%0,%1,%2,%3}, [%4];"
                 : "=r"(r[0]), "=r"(r[1]), "=r"(r[2]), "=r"(r[3]) : "r"(addr));
}
__device__ __forceinline__ void ldsm_x4t(uint32_t* r, uint32_t addr) {
    asm volatile("ldmatrix.sync.aligned.m8n8.x4.trans.shared.b16 {%0,%1,%2,%3}, [%4];"
                 : "=r"(r[0]), "=r"(r[1]), "=r"(r[2]), "=r"(r[3]) : "r"(addr));
}
__device__ __forceinline__ void mma16816(float* c, const uint32_t* a,
                                         uint32_t b0, uint32_t b1) {
    asm volatile(
        "mma.sync.aligned.m16n8k16.row.col.f32.bf16.bf16.f32 "
        "{%0,%1,%2,%3}, {%4,%5,%6,%7}, {%8,%9}, {%0,%1,%2,%3};"
        : "+f"(c[0]), "+f"(c[1]), "+f"(c[2]), "+f"(c[3])
        : "r"(a[0]), "r"(a[1]), "r"(a[2]), "r"(a[3]), "r"(b0), "r"(b1));
}
__device__ __forceinline__ float ex2f(float x) {
    float r; asm("ex2.approx.f32 %0, %1;" : "=f"(r) : "f"(x)); return r;
}
__device__ __forceinline__ uint32_t pk2(float lo, float hi) {   // bf16x2 {lo,hi}
    uint32_t d;
    asm("cvt.rn.bf16x2.f32 %0, %1, %2;" : "=r"(d) : "f"(hi), "f"(lo));
    return d;
}
__device__ __forceinline__ float2 upk2(uint32_t v) {
    __nv_bfloat162 t = *reinterpret_cast<__nv_bfloat162*>(&v);
    return __bfloat1622float2(t);
}

// ============================================================
// splits: fp32 -> bf16 hi/lo
// ============================================================
__device__ __forceinline__ void split4(const float* __restrict__ X,
                                       bf16* __restrict__ Xh,
                                       bf16* __restrict__ Xl, size_t i) {
    float4 v = *(const float4*)&X[i];
    float a[4] = {v.x, v.y, v.z, v.w};
    bf16 h[4], l[4];
    #pragma unroll
    for (int j = 0; j < 4; j++) {
        h[j] = __float2bfloat16_rn(a[j]);
        l[j] = __float2bfloat16_rn(a[j] - __bfloat162float(h[j]));
    }
    *(__nv_bfloat162*)&Xh[i]     = __halves2bfloat162(h[0], h[1]);
    *(__nv_bfloat162*)&Xh[i + 2] = __halves2bfloat162(h[2], h[3]);
    *(__nv_bfloat162*)&Xl[i]     = __halves2bfloat162(l[0], l[1]);
    *(__nv_bfloat162*)&Xl[i + 2] = __halves2bfloat162(l[2], l[3]);
}
__global__ void fsplit(const float* __restrict__ X,
                       bf16* __restrict__ Xh, bf16* __restrict__ Xl) {
    size_t i = (size_t)(blockIdx.x * blockDim.x + threadIdx.x) * 4;
    split4(X, Xh, Xl, i);
}
__global__ void wsplit4(const float* __restrict__ w0, const float* __restrict__ w1,
                        const float* __restrict__ w2, const float* __restrict__ w3,
                        bf16* __restrict__ Wh, bf16* __restrict__ Wl) {
    int z = blockIdx.z;
    const float* W = (z == 0) ? w0 : (z == 1) ? w1 : (z == 2) ? w2 : w3;
    size_t off = (size_t)z * D_MODEL * D_MODEL;
    size_t i = (size_t)(blockIdx.x * blockDim.x + threadIdx.x) * 4;
    split4(W, Wh + off, Wl + off, i);
}

// ============================================================
// hgemm11: C[M,1024] = A @ W via bf16 3-split on mma.sync.
//   CTA tile 128x64, 128 threads = 4 warps of 32x64 (m-split).
//   smem 58KB/CTA, regs ~130 -> THREE CTAs PER SM = 3 independent
//   sync domains (R12 proved domain count is the binding lever).
//   BK=32, 2-stage ring (R9-proven double-buffer), fused term-outer.
// ============================================================
#define AST9 80                          // A smem row stride (40 bf16)
#define BST11 144                        // B smem row stride (72 bf16)
#define ABYT11 (128 * AST9)              // 10240
#define BBYT11 (32 * BST11)              // 4608
#define STG11 (2 * ABYT11 + 2 * BBYT11)  // 29696
#define NST11 32                         // K chunks of 32
#define GEM_SMEM (2 * STG11)             // 59392 -> 3 CTAs/SM

__device__ __forceinline__ void gload11(uint32_t st,
    const bf16* __restrict__ Ah, const bf16* __restrict__ Al,
    const bf16* __restrict__ Bh, const bf16* __restrict__ Bl,
    int m0, int n0, int kk0, int tid)
{
    #pragma unroll
    for (int t = 0; t < 4; t++) {            // A: 128x32 hi+lo (512 chunks ea)
        int idx = tid + (t << 7);
        int r = idx >> 2, c = idx & 3;
        size_t go = (size_t)(m0 + r) * D_MODEL + kk0 + c * 8;
        uint32_t so = st + r * AST9 + c * 16;
        cpa16(so, Ah + go);
        cpa16(so + ABYT11, Al + go);
    }
    #pragma unroll
    for (int t = 0; t < 2; t++) {            // B: 32x64 hi+lo (256 chunks ea)
        int idx = tid + (t << 7);
        int r = idx >> 3, c = idx & 7;
        size_t go = (size_t)(kk0 + r) * D_MODEL + n0 + c * 8;
        uint32_t so = st + 2 * ABYT11 + r * BST11 + c * 16;
        cpa16(so, Bh + go);
        cpa16(so + BBYT11, Bl + go);
    }
}

// fused 3-term pass over one BK=32 chunk, term-outer, 32x64 warp tile
__device__ __forceinline__ void gpass11(float acc[16][4],
    uint32_t aH, uint32_t aL, uint32_t bH, uint32_t bL,
    int wid, int lr, int lc)
{
    #pragma unroll
    for (int k16 = 0; k16 < 2; k16++) {
        uint32_t ah[2][4], al[2][4];
        #pragma unroll
        for (int mt = 0; mt < 2; mt++) {
            uint32_t aoff = (wid * 32 + mt * 16 + lr) * AST9 + k16 * 32 + lc * 16;
            ldsm_x4(ah[mt], aH + aoff);
            ldsm_x4(al[mt], aL + aoff);
        }
        #pragma unroll
        for (int cg = 0; cg < 4; cg++) {     // 4 groups x 16 cols = 64
            uint32_t boff = (k16 * 16 + lr) * BST11 + cg * 32 + lc * 16;
            uint32_t bh4[4], bl4[4];
            ldsm_x4t(bh4, bH + boff);
            ldsm_x4t(bl4, bL + boff);
            // term 1: Ah*Bh
            #pragma unroll
            for (int half = 0; half < 2; half++)
                #pragma unroll
                for (int mt = 0; mt < 2; mt++)
                    mma16816(acc[mt * 8 + cg * 2 + half], ah[mt],
                             bh4[half * 2], bh4[half * 2 + 1]);
            // term 2: Ah*Bl
            #pragma unroll
            for (int half = 0; half < 2; half++)
                #pragma unroll
                for (int mt = 0; mt < 2; mt++)
                    mma16816(acc[mt * 8 + cg * 2 + half], ah[mt],
                             bl4[half * 2], bl4[half * 2 + 1]);
            // term 3: Al*Bh
            #pragma unroll
            for (int half = 0; half < 2; half++)
                #pragma unroll
                for (int mt = 0; mt < 2; mt++)
                    mma16816(acc[mt * 8 + cg * 2 + half], al[mt],
                             bh4[half * 2], bh4[half * 2 + 1]);
        }
    }
}

template<int MODE>
__global__ __launch_bounds__(128, 3) void hgemm11(
    const bf16* __restrict__ Ah, const bf16* __restrict__ Al,
    const bf16* __restrict__ BhB, const bf16* __restrict__ BlB,
    float* __restrict__ C,
    bf16* __restrict__ Ch0, bf16* __restrict__ Cl0,
    bf16* __restrict__ Ch1, bf16* __restrict__ Cl1,
    bf16* __restrict__ Ch2, bf16* __restrict__ Cl2)
{
    extern __shared__ char dsm[];
    const uint32_t sb = smem_u32(dsm);

    const int tid = threadIdx.x;
    const int wid = tid >> 5;               // 0..3 (m-split, 32 rows each)
    const int lane = tid & 31;
    const int lr = lane & 15, lc = lane >> 4;
    const int m0 = blockIdx.y << 7;
    const int n0 = blockIdx.x << 6;         // 64-wide n tiles
    const int z  = blockIdx.z;

    const bf16* Bh = BhB + (size_t)z * D_MODEL * D_MODEL;
    const bf16* Bl = BlB + (size_t)z * D_MODEL * D_MODEL;

    float acc[16][4];
    #pragma unroll
    for (int i = 0; i < 16; i++)
        #pragma unroll
        for (int j = 0; j < 4; j++) acc[i][j] = 0.f;

    gload11(sb, Ah, Al, Bh, Bl, m0, n0, 0, tid);
    CP_COMMIT();

    #pragma unroll 1
    for (int s = 0; s < NST11; s++) {
        if (s + 1 < NST11) {
            gload11(sb + ((s + 1) & 1) * STG11, Ah, Al, Bh, Bl,
                    m0, n0, (s + 1) << 5, tid);
            CP_COMMIT();
            CP_WAIT1();
        } else {
            CP_WAIT0();
        }
        __syncthreads();

        const uint32_t base = sb + (s & 1) * STG11;
        gpass11(acc, base, base + ABYT11,
                base + 2 * ABYT11, base + 2 * ABYT11 + BBYT11,
                wid, lr, lc);
        __syncthreads();
    }

    const int g = lane >> 2, tg = lane & 3;
    const float scale = (MODE == 1 && z == 0) ? QSC : 1.0f;
    bf16* Ch = (z == 0) ? Ch0 : (z == 1) ? Ch1 : Ch2;
    bf16* Cl = (z == 0) ? Cl0 : (z == 1) ? Cl1 : Cl2;

    #pragma unroll
    for (int mt = 0; mt < 2; mt++) {
        int row = m0 + wid * 32 + mt * 16 + g;
        #pragma unroll
        for (int nt = 0; nt < 8; nt++) {
            int col = n0 + nt * 8 + tg * 2;
            float* ac = acc[mt * 8 + nt];
            if (MODE == 0) {
                float* cp = &C[(size_t)row * D_MODEL + col];
                *(float2*)cp = make_float2(ac[0], ac[1]);
                *(float2*)(cp + 8 * D_MODEL) = make_float2(ac[2], ac[3]);
            } else {
                float v0 = ac[0] * scale, v1 = ac[1] * scale;
                float v2 = ac[2] * scale, v3 = ac[3] * scale;
                uint32_t h01 = pk2(v0, v1), h23 = pk2(v2, v3);
                float2 f01 = upk2(h01), f23 = upk2(h23);
                size_t o0 = (size_t)row * D_MODEL + col;
                size_t o1 = o0 + 8 * D_MODEL;
                *(uint32_t*)&Ch[o0] = h01;
                *(uint32_t*)&Ch[o1] = h23;
                *(uint32_t*)&Cl[o0] = pk2(v0 - f01.x, v1 - f01.y);
                *(uint32_t*)&Cl[o1] = pk2(v2 - f23.x, v3 - f23.y);
            }
        }
    }
}

// ============================================================
// attn_mma4 (R12, unchanged): flash attention, 128 queries/CTA,
// 4 warps x 32 q-rows, 2 CTAs/SM.
// ============================================================
#define AST 144
#define QTB4  (128 * AST)                // one 128x64 bf16 Q tile = 18432
#define KVB   (64 * AST)                 // one 64x64 bf16 tile = 9216
#define KVST  (4 * KVB)                  // Kh,Kl,Vh,Vl per stage = 36864
#define KVOFF4 (2 * QTB4)                // 36864
#define ATT_SMEM (KVOFF4 + 2 * KVST)     // 110592 -> 2 CTAs/SM

__device__ __forceinline__ void kvload4(uint32_t st,
    const bf16* __restrict__ Kh, const bf16* __restrict__ Kl,
    const bf16* __restrict__ Vh, const bf16* __restrict__ Vl,
    size_t gbase, int tid)
{
    #pragma unroll
    for (int t = 0; t < 4; t++) {
        int idx = tid + (t << 7);
        int r = idx >> 3, c = idx & 7;
        size_t go = gbase + (size_t)r * D_MODEL + c * 8;
        uint32_t so = st + r * AST + c * 16;
        cpa16(so,           Kh + go);
        cpa16(so + KVB,     Kl + go);
        cpa16(so + 2 * KVB, Vh + go);
        cpa16(so + 3 * KVB, Vl + go);
    }
}

__global__ __launch_bounds__(128, 2) void attn_mma4(
    const bf16* __restrict__ Qh, const bf16* __restrict__ Ql,
    const bf16* __restrict__ Kh, const bf16* __restrict__ Kl,
    const bf16* __restrict__ Vh, const bf16* __restrict__ Vl,
    bf16* __restrict__ Oh, bf16* __restrict__ Ol)
{
    extern __shared__ char dsm[];
    const uint32_t sb = smem_u32(dsm);

    const int tid = threadIdx.x;
    const int wid = tid >> 5;
    const int lane = tid & 31;
    const int lr = lane & 15, lc = lane >> 4;
    const int g = lane >> 2, tg = lane & 3;
    const int qb = blockIdx.x, h = blockIdx.y, b = blockIdx.z;
    const size_t qrow0 = (size_t)(b * SEQ + qb * 128);
    const size_t hcol = h * DH;

    #pragma unroll
    for (int t = 0; t < 8; t++) {
        int idx = tid + (t << 7);
        int r = idx >> 3, c = idx & 7;
        size_t go = (qrow0 + r) * D_MODEL + hcol + c * 8;
        uint32_t so = sb + r * AST + c * 16;
        cpa16(so, Qh + go);
        cpa16(so + QTB4, Ql + go);
    }
    CP_COMMIT();

    kvload4(sb + KVOFF4, Kh, Kl, Vh, Vl, (size_t)(b * SEQ) * D_MODEL + hcol, tid);
    CP_COMMIT();

    float acco[16][4];
    #pragma unroll
    for (int i = 0; i < 16; i++)
        #pragma unroll
        for (int j = 0; j < 4; j++) acco[i][j] = 0.f;
    float mrow[4] = {-1e30f, -1e30f, -1e30f, -1e30f};
    float lrow[4] = {0.f, 0.f, 0.f, 0.f};

    #pragma unroll 1
    for (int kb = 0; kb < 16; kb++) {
        if (kb < 15)
            kvload4(sb + KVOFF4 + ((kb + 1) & 1) * KVST, Kh, Kl, Vh, Vl,
                    (size_t)(b * SEQ + (kb + 1) * 64) * D_MODEL + hcol, tid);
        CP_COMMIT();
        CP_WAIT1();
        __syncthreads();

        const uint32_t kst = sb + KVOFF4 + (kb & 1) * KVST;
        const uint32_t khT = kst, klT = kst + KVB;
        const uint32_t vhT = kst + 2 * KVB, vlT = kst + 3 * KVB;

        float accs[16][4];
        #pragma unroll
        for (int i = 0; i < 16; i++)
            #pragma unroll
            for (int j = 0; j < 4; j++) accs[i][j] = 0.f;

        #pragma unroll
        for (int kt = 0; kt < 4; kt++) {
            uint32_t ah[2][4], al[2][4], kfh[4][4], kfl[4][4];
            #pragma unroll
            for (int mt = 0; mt < 2; mt++) {
                uint32_t qoff = (wid * 32 + mt * 16 + lr) * AST + kt * 32 + lc * 16;
                ldsm_x4(ah[mt], sb + qoff);
                ldsm_x4(al[mt], sb + QTB4 + qoff);
            }
            #pragma unroll
            for (int j = 0; j < 4; j++) {
                uint32_t koff = (j * 16 + lr) * AST + kt * 32 + lc * 16;
                ldsm_x4(kfh[j], khT + koff);
                ldsm_x4(kfl[j], klT + koff);
            }
            #pragma unroll
            for (int mt = 0; mt < 2; mt++)
                #pragma unroll
                for (int j = 0; j < 4; j++) {
                    mma16816(accs[mt * 8 + 2 * j],     ah[mt], kfh[j][0], kfh[j][2]);
                    mma16816(accs[mt * 8 + 2 * j + 1], ah[mt], kfh[j][1], kfh[j][3]);
                }
            #pragma unroll
            for (int mt = 0; mt < 2; mt++)
                #pragma unroll
                for (int j = 0; j < 4; j++) {
                    mma16816(accs[mt * 8 + 2 * j],     ah[mt], kfl[j][0], kfl[j][2]);
                    mma16816(accs[mt * 8 + 2 * j + 1], ah[mt], kfl[j][1], kfl[j][3]);
                }
            #pragma unroll
            for (int mt = 0; mt < 2; mt++)
                #pragma unroll
                for (int j = 0; j < 4; j++) {
                    mma16816(accs[mt * 8 + 2 * j],     al[mt], kfh[j][0], kfh[j][2]);
                    mma16816(accs[mt * 8 + 2 * j + 1], al[mt], kfh[j][1], kfh[j][3]);
                }
        }

        #pragma unroll
        for (int mt = 0; mt < 2; mt++) {
            float mx0 = -1e30f, mx1 = -1e30f;
            #pragma unroll
            for (int nt = 0; nt < 8; nt++) {
                mx0 = fmaxf(mx0, fmaxf(accs[mt * 8 + nt][0], accs[mt * 8 + nt][1]));
                mx1 = fmaxf(mx1, fmaxf(accs[mt * 8 + nt][2], accs[mt * 8 + nt][3]));
            }
            mx0 = fmaxf(mx0, __shfl_xor_sync(0xffffffffu, mx0, 1));
            mx0 = fmaxf(mx0, __shfl_xor_sync(0xffffffffu, mx0, 2));
            mx1 = fmaxf(mx1, __shfl_xor_sync(0xffffffffu, mx1, 1));
            mx1 = fmaxf(mx1, __shfl_xor_sync(0xffffffffu, mx1, 2));
            float mn0 = fmaxf(mrow[mt * 2],     mx0);
            float mn1 = fmaxf(mrow[mt * 2 + 1], mx1);
            float al0 = ex2f(mrow[mt * 2]     - mn0);
            float al1 = ex2f(mrow[mt * 2 + 1] - mn1);
            mrow[mt * 2] = mn0; mrow[mt * 2 + 1] = mn1;
            float s0 = 0.f, s1 = 0.f;
            #pragma unroll
            for (int nt = 0; nt < 8; nt++) {
                float* a = accs[mt * 8 + nt];
                a[0] = ex2f(a[0] - mn0);
                a[1] = ex2f(a[1] - mn0);
                a[2] = ex2f(a[2] - mn1);
                a[3] = ex2f(a[3] - mn1);
                s0 += a[0] + a[1];
                s1 += a[2] + a[3];
            }
            s0 += __shfl_xor_sync(0xffffffffu, s0, 1);
            s0 += __shfl_xor_sync(0xffffffffu, s0, 2);
            s1 += __shfl_xor_sync(0xffffffffu, s1, 1);
            s1 += __shfl_xor_sync(0xffffffffu, s1, 2);
            lrow[mt * 2]     = lrow[mt * 2]     * al0 + s0;
            lrow[mt * 2 + 1] = lrow[mt * 2 + 1] * al1 + s1;
            #pragma unroll
            for (int nt = 0; nt < 8; nt++) {
                acco[mt * 8 + nt][0] *= al0; acco[mt * 8 + nt][1] *= al0;
                acco[mt * 8 + nt][2] *= al1; acco[mt * 8 + nt][3] *= al1;
            }
        }

        #pragma unroll
        for (int kt = 0; kt < 4; kt++) {
            uint32_t vbh[4][4], vbl[4][4];
            #pragma unroll
            for (int cg = 0; cg < 4; cg++) {
                uint32_t voff = (kt * 16 + lr) * AST + cg * 32 + lc * 16;
                ldsm_x4t(vbh[cg], vhT + voff);
                ldsm_x4t(vbl[cg], vlT + voff);
            }
            uint32_t ph[2][4], pl[2][4];
            #pragma unroll
            for (int mt = 0; mt < 2; mt++) {
                float* s0 = accs[mt * 8 + 2 * kt];
                float* s1 = accs[mt * 8 + 2 * kt + 1];
                ph[mt][0] = pk2(s0[0], s0[1]);
                ph[mt][1] = pk2(s0[2], s0[3]);
                ph[mt][2] = pk2(s1[0], s1[1]);
                ph[mt][3] = pk2(s1[2], s1[3]);
                float2 f0 = upk2(ph[mt][0]), f1 = upk2(ph[mt][1]);
                float2 f2 = upk2(ph[mt][2]), f3 = upk2(ph[mt][3]);
                pl[mt][0] = pk2(s0[0] - f0.x, s0[1] - f0.y);
                pl[mt][1] = pk2(s0[2] - f1.x, s0[3] - f1.y);
                pl[mt][2] = pk2(s1[0] - f2.x, s1[1] - f2.y);
                pl[mt][3] = pk2(s1[2] - f3.x, s1[3] - f3.y);
            }
            #pragma unroll
            for (int mt = 0; mt < 2; mt++)
                #pragma unroll
                for (int nt = 0; nt < 8; nt++)
                    mma16816(acco[mt * 8 + nt], ph[mt],
                             vbh[nt >> 1][(nt & 1) * 2],
                             vbh[nt >> 1][(nt & 1) * 2 + 1]);
            #pragma unroll
            for (int mt = 0; mt < 2; mt++)
                #pragma unroll
                for (int nt = 0; nt < 8; nt++)
                    mma16816(acco[mt * 8 + nt], pl[mt],
                             vbh[nt >> 1][(nt & 1) * 2],
                             vbh[nt >> 1][(nt & 1) * 2 + 1]);
            #pragma unroll
            for (int mt = 0; mt < 2; mt++)
                #pragma unroll
                for (int nt = 0; nt < 8; nt++)
                    mma16816(acco[mt * 8 + nt], ph[mt],
                             vbl[nt >> 1][(nt & 1) * 2],
                             vbl[nt >> 1][(nt & 1) * 2 + 1]);
        }
        __syncthreads();
    }

    #pragma unroll
    for (int mt = 0; mt < 2; mt++) {
        float inv0 = 1.f / lrow[mt * 2];
        float inv1 = 1.f / lrow[mt * 2 + 1];
        size_t r0 = (qrow0 + wid * 32 + mt * 16 + g) * D_MODEL + hcol;
        size_t r1 = r0 + 8 * D_MODEL;
        #pragma unroll
        for (int nt = 0; nt < 8; nt++) {
            int col = nt * 8 + tg * 2;
            float v0 = acco[mt * 8 + nt][0] * inv0;
            float v1 = acco[mt * 8 + nt][1] * inv0;
            float v2 = acco[mt * 8 + nt][2] * inv1;
            float v3 = acco[mt * 8 + nt][3] * inv1;
            uint32_t h01 = pk2(v0, v1), h23 = pk2(v2, v3);
            float2 f01 = upk2(h01), f23 = upk2(h23);
            *(uint32_t*)&Oh[r0 + col] = h01;
            *(uint32_t*)&Oh[r1 + col] = h23;
            *(uint32_t*)&Ol[r0 + col] = pk2(v0 - f01.x, v1 - f01.y);
            *(uint32_t*)&Ol[r1 + col] = pk2(v2 - f23.x, v3 - f23.y);
        }
    }
}

// ============================================================
extern "C" void kernel_launch(void* const* d_in, const int* in_sizes, int n_in,
                              void* d_out, int out_size)
{
    const float* x = (const float*)d_in[0];
    float* out = (float*)d_out;

    bf16 *xh, *xl, *qh, *ql, *kh, *kl, *vh, *vl, *oh, *ol, *bh, *bl;
    cudaGetSymbolAddress((void**)&xh, g_xh);
    cudaGetSymbolAddress((void**)&xl, g_xl);
    cudaGetSymbolAddress((void**)&qh, g_Qh);
    cudaGetSymbolAddress((void**)&ql, g_Ql);
    cudaGetSymbolAddress((void**)&kh, g_Kh);
    cudaGetSymbolAddress((void**)&kl, g_Kl);
    cudaGetSymbolAddress((void**)&vh, g_Vh);
    cudaGetSymbolAddress((void**)&vl, g_Vl);
    cudaGetSymbolAddress((void**)&oh, g_Oh);
    cudaGetSymbolAddress((void**)&ol, g_Ol);
    cudaGetSymbolAddress((void**)&bh, g_Wh);
    cudaGetSymbolAddress((void**)&bl, g_Wl);
    const size_t WSTR = (size_t)D_MODEL * D_MODEL;

    static int cfg_done = 0;
    if (!cfg_done) {
        cudaFuncSetAttribute(hgemm11<0>,
            cudaFuncAttributeMaxDynamicSharedMemorySize, GEM_SMEM);
        cudaFuncSetAttribute(hgemm11<1>,
            cudaFuncAttributeMaxDynamicSharedMemorySize, GEM_SMEM);
        cudaFuncSetAttribute(attn_mma4,
            cudaFuncAttributeMaxDynamicSharedMemorySize, ATT_SMEM);
        cfg_done = 1;
    }

    // splits: x, then all 4 weights in one launch
    fsplit<<<MROWS * D_MODEL / 1024, 256>>>(x, xh, xl);
    wsplit4<<<dim3(D_MODEL * D_MODEL / 1024, 1, 4), 256>>>(
        (const float*)d_in[1], (const float*)d_in[2],
        (const float*)d_in[3], (const float*)d_in[4], bh, bl);

    // QKV projections fused into one launch (grid.z selects W / output)
    hgemm11<1><<<dim3(D_MODEL / 64, MROWS / 128, 3), 128, GEM_SMEM>>>(
        xh, xl, bh, bl, nullptr, qh, ql, kh, kl, vh, vl);

    attn_mma4<<<dim3(SEQ / 128, HEADS, BATCH), 128, ATT_SMEM>>>(
        qh, ql, kh, kl, vh, vl, oh, ol);

    // final projection (W index 3)
    hgemm11<0><<<dim3(D_MODEL / 64, MROWS / 128, 1), 128, GEM_SMEM>>>(
        oh, ol, bh + 3 * WSTR, bl + 3 * WSTR, out,
        nullptr, nullptr, nullptr, nullptr, nullptr, nullptr);
}

// round 16
// speedup vs baseline: 1.2684x; 1.2424x over previous
#include <cuda_runtime.h>
#include <cuda_fp16.h>
#include <math.h>
#include <cstdint>

#define D_MODEL 1024
#define HEADS   16
#define DH      64
#define SEQ     1024
#define BATCH   8
#define MROWS   (BATCH*SEQ)   // 8192

typedef __half hf;

// ---- scratch (no cudaMalloc allowed) ----
__device__ hf g_xh[MROWS*D_MODEL];
__device__ hf g_xl[MROWS*D_MODEL];
__device__ hf g_Qh[MROWS*D_MODEL];
__device__ hf g_Ql[MROWS*D_MODEL];
__device__ hf g_Kh[MROWS*D_MODEL];
__device__ hf g_Kl[MROWS*D_MODEL];
__device__ hf g_Vh[MROWS*D_MODEL];
__device__ hf g_Vl[MROWS*D_MODEL];
__device__ hf g_Oh[MROWS*D_MODEL];
__device__ hf g_Wh[4][D_MODEL*D_MODEL];  // natural [k][n]
__device__ hf g_Wl[4][D_MODEL*D_MODEL];

#define QSC (0.125f * 1.44269504088896f)   // 1/sqrt(dh) * log2(e)

// ============================================================
// PTX helpers (sm_80-era only; tcgen05 unavailable at .target sm_103)
// ============================================================
__device__ __forceinline__ uint32_t smem_u32(const void* p) {
    uint32_t a;
    asm("{ .reg .u64 t; cvta.to.shared.u64 t, %1; cvt.u32.u64 %0, t; }"
        : "=r"(a) : "l"(p));
    return a;
}
__device__ __forceinline__ void cpa16(uint32_t dst, const void* src) {
    asm volatile("cp.async.cg.shared.global [%0], [%1], 16;"
                 :: "r"(dst), "l"(src) : "memory");
}
#define CP_COMMIT() asm volatile("cp.async.commit_group;" ::: "memory")
#define CP_WAIT1()  asm volatile("cp.async.wait_group 1;" ::: "memory")
#define CP_WAIT0()  asm volatile("cp.async.wait_group 0;" ::: "memory")

__device__ __forceinline__ void ldsm_x4(uint32_t* r, uint32_t addr) {
    asm volatile("ldmatrix.sync.aligned.m8n8.x4.shared.b16 {%0,%1,%2,%3}, [%4];"
                 : "=r"(r[0]), "=r"(r[1]), "=r"(r[2]), "=r"(r[3]) : "r"(addr));
}
__device__ __forceinline__ void ldsm_x4t(uint32_t* r, uint32_t addr) {
    asm volatile("ldmatrix.sync.aligned.m8n8.x4.trans.shared.b16 {%0,%1,%2,%3}, [%4];"
                 : "=r"(r[0]), "=r"(r[1]), "=r"(r[2]), "=r"(r[3]) : "r"(addr));
}
// fp16 mma, fp32 accumulate
__device__ __forceinline__ void mma16816h(float* c, const uint32_t* a,
                                          uint32_t b0, uint32_t b1) {
    asm volatile(
        "mma.sync.aligned.m16n8k16.row.col.f32.f16.f16.f32 "
        "{%0,%1,%2,%3}, {%4,%5,%6,%7}, {%8,%9}, {%0,%1,%2,%3};"
        : "+f"(c[0]), "+f"(c[1]), "+f"(c[2]), "+f"(c[3])
        : "r"(a[0]), "r"(a[1]), "r"(a[2]), "r"(a[3]), "r"(b0), "r"(b1));
}
__device__ __forceinline__ float ex2f(float x) {
    float r; asm("ex2.approx.f32 %0, %1;" : "=f"(r) : "f"(x)); return r;
}
__device__ __forceinline__ uint32_t pk2h(float lo, float hi) {   // f16x2 {lo,hi}
    __half2 t = __floats2half2_rn(lo, hi);
    return *reinterpret_cast<uint32_t*>(&t);
}
__device__ __forceinline__ float2 upk2h(uint32_t v) {
    __half2 t = *reinterpret_cast<__half2*>(&v);
    return __half22float2(t);
}

// ============================================================
// splits: fp32 -> fp16 hi/lo
// ============================================================
__device__ __forceinline__ void split4(const float* __restrict__ X,
                                       hf* __restrict__ Xh,
                                       hf* __restrict__ Xl, size_t i) {
    float4 v = *(const float4*)&X[i];
    float a[4] = {v.x, v.y, v.z, v.w};
    hf h[4], l[4];
    #pragma unroll
    for (int j = 0; j < 4; j++) {
        h[j] = __float2half_rn(a[j]);
        l[j] = __float2half_rn(a[j] - __half2float(h[j]));
    }
    *(__half2*)&Xh[i]     = __halves2half2(h[0], h[1]);
    *(__half2*)&Xh[i + 2] = __halves2half2(h[2], h[3]);
    *(__half2*)&Xl[i]     = __halves2half2(l[0], l[1]);
    *(__half2*)&Xl[i + 2] = __halves2half2(l[2], l[3]);
}
__global__ void fsplit(const float* __restrict__ X,
                       hf* __restrict__ Xh, hf* __restrict__ Xl) {
    size_t i = (size_t)(blockIdx.x * blockDim.x + threadIdx.x) * 4;
    split4(X, Xh, Xl, i);
}
__global__ void wsplit4(const float* __restrict__ w0, const float* __restrict__ w1,
                        const float* __restrict__ w2, const float* __restrict__ w3,
                        hf* __restrict__ Wh, hf* __restrict__ Wl) {
    int z = blockIdx.z;
    const float* W = (z == 0) ? w0 : (z == 1) ? w1 : (z == 2) ? w2 : w3;
    size_t off = (size_t)z * D_MODEL * D_MODEL;
    size_t i = (size_t)(blockIdx.x * blockDim.x + threadIdx.x) * 4;
    split4(W, Wh + off, Wl + off, i);
}

// ============================================================
// hgemm12: C[M,1024] = A @ W via fp16 split on mma.sync.
//   CTA tile 128x64, 128 threads = 4 warps of 32x64 (m-split),
//   3 CTAs/SM, BK=32 double-buffered (R15-proven shape).
//   Q/K (z=0,1): 3-term split.  V (z=2) and out-proj (MODE 0):
//   SINGLE-PASS fp16 (precision analysis: ~4e-4 rel, no logit
//   amplification on these paths) -> 2/3 of their mma work gone.
// ============================================================
#define AST9 80                          // A smem row stride (40 hf)
#define BST11 144                        // B smem row stride (72 hf)
#define ABYT11 (128 * AST9)              // 10240
#define BBYT11 (32 * BST11)              // 4608
#define STG11 (2 * ABYT11 + 2 * BBYT11)  // 29696
#define NST11 32                         // K chunks of 32
#define GEM_SMEM (2 * STG11)             // 59392 -> 3 CTAs/SM

__device__ __forceinline__ void gload12(uint32_t st,
    const hf* __restrict__ Ah, const hf* __restrict__ Al,
    const hf* __restrict__ Bh, const hf* __restrict__ Bl,
    int m0, int n0, int kk0, int tid, bool lo)
{
    #pragma unroll
    for (int t = 0; t < 4; t++) {            // A: 128x32 (512 chunks)
        int idx = tid + (t << 7);
        int r = idx >> 2, c = idx & 3;
        size_t go = (size_t)(m0 + r) * D_MODEL + kk0 + c * 8;
        uint32_t so = st + r * AST9 + c * 16;
        cpa16(so, Ah + go);
        if (lo) cpa16(so + ABYT11, Al + go);
    }
    #pragma unroll
    for (int t = 0; t < 2; t++) {            // B: 32x64 (256 chunks)
        int idx = tid + (t << 7);
        int r = idx >> 3, c = idx & 7;
        size_t go = (size_t)(kk0 + r) * D_MODEL + n0 + c * 8;
        uint32_t so = st + 2 * ABYT11 + r * BST11 + c * 16;
        cpa16(so, Bh + go);
        if (lo) cpa16(so + BBYT11, Bl + go);
    }
}

// fused 3-term pass over one BK=32 chunk, term-outer, 32x64 warp tile
__device__ __forceinline__ void gpass3(float acc[16][4],
    uint32_t aH, uint32_t aL, uint32_t bH, uint32_t bL,
    int wid, int lr, int lc)
{
    #pragma unroll
    for (int k16 = 0; k16 < 2; k16++) {
        uint32_t ah[2][4], al[2][4];
        #pragma unroll
        for (int mt = 0; mt < 2; mt++) {
            uint32_t aoff = (wid * 32 + mt * 16 + lr) * AST9 + k16 * 32 + lc * 16;
            ldsm_x4(ah[mt], aH + aoff);
            ldsm_x4(al[mt], aL + aoff);
        }
        #pragma unroll
        for (int cg = 0; cg < 4; cg++) {
            uint32_t boff = (k16 * 16 + lr) * BST11 + cg * 32 + lc * 16;
            uint32_t bh4[4], bl4[4];
            ldsm_x4t(bh4, bH + boff);
            ldsm_x4t(bl4, bL + boff);
            #pragma unroll
            for (int half = 0; half < 2; half++)
                #pragma unroll
                for (int mt = 0; mt < 2; mt++)
                    mma16816h(acc[mt * 8 + cg * 2 + half], ah[mt],
                              bh4[half * 2], bh4[half * 2 + 1]);
            #pragma unroll
            for (int half = 0; half < 2; half++)
                #pragma unroll
                for (int mt = 0; mt < 2; mt++)
                    mma16816h(acc[mt * 8 + cg * 2 + half], ah[mt],
                              bl4[half * 2], bl4[half * 2 + 1]);
            #pragma unroll
            for (int half = 0; half < 2; half++)
                #pragma unroll
                for (int mt = 0; mt < 2; mt++)
                    mma16816h(acc[mt * 8 + cg * 2 + half], al[mt],
                              bh4[half * 2], bh4[half * 2 + 1]);
        }
    }
}

// single-term pass (hi*hi only)
__device__ __forceinline__ void gpass1(float acc[16][4],
    uint32_t aH, uint32_t bH, int wid, int lr, int lc)
{
    #pragma unroll
    for (int k16 = 0; k16 < 2; k16++) {
        uint32_t ah[2][4];
        #pragma unroll
        for (int mt = 0; mt < 2; mt++) {
            uint32_t aoff = (wid * 32 + mt * 16 + lr) * AST9 + k16 * 32 + lc * 16;
            ldsm_x4(ah[mt], aH + aoff);
        }
        #pragma unroll
        for (int cg = 0; cg < 4; cg++) {
            uint32_t boff = (k16 * 16 + lr) * BST11 + cg * 32 + lc * 16;
            uint32_t bh4[4];
            ldsm_x4t(bh4, bH + boff);
            #pragma unroll
            for (int half = 0; half < 2; half++)
                #pragma unroll
                for (int mt = 0; mt < 2; mt++)
                    mma16816h(acc[mt * 8 + cg * 2 + half], ah[mt],
                              bh4[half * 2], bh4[half * 2 + 1]);
        }
    }
}

template<int MODE>
__global__ __launch_bounds__(128, 3) void hgemm12(
    const hf* __restrict__ Ah, const hf* __restrict__ Al,
    const hf* __restrict__ BhB, const hf* __restrict__ BlB,
    float* __restrict__ C,
    hf* __restrict__ Ch0, hf* __restrict__ Cl0,
    hf* __restrict__ Ch1, hf* __restrict__ Cl1,
    hf* __restrict__ Ch2, hf* __restrict__ Cl2)
{
    extern __shared__ char dsm[];
    const uint32_t sb = smem_u32(dsm);

    const int tid = threadIdx.x;
    const int wid = tid >> 5;
    const int lane = tid & 31;
    const int lr = lane & 15, lc = lane >> 4;
    const int m0 = blockIdx.y << 7;
    const int n0 = blockIdx.x << 6;
    const int z  = blockIdx.z;
    const bool three = (MODE == 1) && (z != 2);   // V and out-proj: 1-term

    const hf* Bh = BhB + (size_t)z * D_MODEL * D_MODEL;
    const hf* Bl = BlB + (size_t)z * D_MODEL * D_MODEL;

    float acc[16][4];
    #pragma unroll
    for (int i = 0; i < 16; i++)
        #pragma unroll
        for (int j = 0; j < 4; j++) acc[i][j] = 0.f;

    gload12(sb, Ah, Al, Bh, Bl, m0, n0, 0, tid, three);
    CP_COMMIT();

    #pragma unroll 1
    for (int s = 0; s < NST11; s++) {
        if (s + 1 < NST11) {
            gload12(sb + ((s + 1) & 1) * STG11, Ah, Al, Bh, Bl,
                    m0, n0, (s + 1) << 5, tid, three);
            CP_COMMIT();
            CP_WAIT1();
        } else {
            CP_WAIT0();
        }
        __syncthreads();

        const uint32_t base = sb + (s & 1) * STG11;
        if (three)
            gpass3(acc, base, base + ABYT11,
                   base + 2 * ABYT11, base + 2 * ABYT11 + BBYT11,
                   wid, lr, lc);
        else
            gpass1(acc, base, base + 2 * ABYT11, wid, lr, lc);
        __syncthreads();
    }

    const int g = lane >> 2, tg = lane & 3;
    const float scale = (MODE == 1 && z == 0) ? QSC : 1.0f;
    hf* Ch = (z == 0) ? Ch0 : (z == 1) ? Ch1 : Ch2;
    hf* Cl = (z == 0) ? Cl0 : (z == 1) ? Cl1 : Cl2;

    #pragma unroll
    for (int mt = 0; mt < 2; mt++) {
        int row = m0 + wid * 32 + mt * 16 + g;
        #pragma unroll
        for (int nt = 0; nt < 8; nt++) {
            int col = n0 + nt * 8 + tg * 2;
            float* ac = acc[mt * 8 + nt];
            if (MODE == 0) {
                float* cp = &C[(size_t)row * D_MODEL + col];
                *(float2*)cp = make_float2(ac[0], ac[1]);
                *(float2*)(cp + 8 * D_MODEL) = make_float2(ac[2], ac[3]);
            } else {
                float v0 = ac[0] * scale, v1 = ac[1] * scale;
                float v2 = ac[2] * scale, v3 = ac[3] * scale;
                uint32_t h01 = pk2h(v0, v1), h23 = pk2h(v2, v3);
                float2 f01 = upk2h(h01), f23 = upk2h(h23);
                size_t o0 = (size_t)row * D_MODEL + col;
                size_t o1 = o0 + 8 * D_MODEL;
                *(uint32_t*)&Ch[o0] = h01;
                *(uint32_t*)&Ch[o1] = h23;
                *(uint32_t*)&Cl[o0] = pk2h(v0 - f01.x, v1 - f01.y);
                *(uint32_t*)&Cl[o1] = pk2h(v2 - f23.x, v3 - f23.y);
            }
        }
    }
}

// ============================================================
// attn_mma5: R12 attention structure, fp16 operands throughout.
// 128 queries/CTA, 4 warps x 32 q-rows, 2 CTAs/SM. Output: Oh
// fp16 single (out-proj is 1-term).
// ============================================================
#define AST 144
#define QTB4  (128 * AST)
#define KVB   (64 * AST)
#define KVST  (4 * KVB)
#define KVOFF4 (2 * QTB4)
#define ATT_SMEM (KVOFF4 + 2 * KVST)     // 110592 -> 2 CTAs/SM

__device__ __forceinline__ void kvload4(uint32_t st,
    const hf* __restrict__ Kh, const hf* __restrict__ Kl,
    const hf* __restrict__ Vh, const hf* __restrict__ Vl,
    size_t gbase, int tid)
{
    #pragma unroll
    for (int t = 0; t < 4; t++) {
        int idx = tid + (t << 7);
        int r = idx >> 3, c = idx & 7;
        size_t go = gbase + (size_t)r * D_MODEL + c * 8;
        uint32_t so = st + r * AST + c * 16;
        cpa16(so,           Kh + go);
        cpa16(so + KVB,     Kl + go);
        cpa16(so + 2 * KVB, Vh + go);
        cpa16(so + 3 * KVB, Vl + go);
    }
}

__global__ __launch_bounds__(128, 2) void attn_mma5(
    const hf* __restrict__ Qh, const hf* __restrict__ Ql,
    const hf* __restrict__ Kh, const hf* __restrict__ Kl,
    const hf* __restrict__ Vh, const hf* __restrict__ Vl,
    hf* __restrict__ Oh)
{
    extern __shared__ char dsm[];
    const uint32_t sb = smem_u32(dsm);

    const int tid = threadIdx.x;
    const int wid = tid >> 5;
    const int lane = tid & 31;
    const int lr = lane & 15, lc = lane >> 4;
    const int g = lane >> 2, tg = lane & 3;
    const int qb = blockIdx.x, h = blockIdx.y, b = blockIdx.z;
    const size_t qrow0 = (size_t)(b * SEQ + qb * 128);
    const size_t hcol = h * DH;

    #pragma unroll
    for (int t = 0; t < 8; t++) {
        int idx = tid + (t << 7);
        int r = idx >> 3, c = idx & 7;
        size_t go = (qrow0 + r) * D_MODEL + hcol + c * 8;
        uint32_t so = sb + r * AST + c * 16;
        cpa16(so, Qh + go);
        cpa16(so + QTB4, Ql + go);
    }
    CP_COMMIT();

    kvload4(sb + KVOFF4, Kh, Kl, Vh, Vl, (size_t)(b * SEQ) * D_MODEL + hcol, tid);
    CP_COMMIT();

    float acco[16][4];
    #pragma unroll
    for (int i = 0; i < 16; i++)
        #pragma unroll
        for (int j = 0; j < 4; j++) acco[i][j] = 0.f;
    float mrow[4] = {-1e30f, -1e30f, -1e30f, -1e30f};
    float lrow[4] = {0.f, 0.f, 0.f, 0.f};

    #pragma unroll 1
    for (int kb = 0; kb < 16; kb++) {
        if (kb < 15)
            kvload4(sb + KVOFF4 + ((kb + 1) & 1) * KVST, Kh, Kl, Vh, Vl,
                    (size_t)(b * SEQ + (kb + 1) * 64) * D_MODEL + hcol, tid);
        CP_COMMIT();
        CP_WAIT1();
        __syncthreads();

        const uint32_t kst = sb + KVOFF4 + (kb & 1) * KVST;
        const uint32_t khT = kst, klT = kst + KVB;
        const uint32_t vhT = kst + 2 * KVB, vlT = kst + 3 * KVB;

        float accs[16][4];
        #pragma unroll
        for (int i = 0; i < 16; i++)
            #pragma unroll
            for (int j = 0; j < 4; j++) accs[i][j] = 0.f;

        #pragma unroll
        for (int kt = 0; kt < 4; kt++) {
            uint32_t ah[2][4], al[2][4], kfh[4][4], kfl[4][4];
            #pragma unroll
            for (int mt = 0; mt < 2; mt++) {
                uint32_t qoff = (wid * 32 + mt * 16 + lr) * AST + kt * 32 + lc * 16;
                ldsm_x4(ah[mt], sb + qoff);
                ldsm_x4(al[mt], sb + QTB4 + qoff);
            }
            #pragma unroll
            for (int j = 0; j < 4; j++) {
                uint32_t koff = (j * 16 + lr) * AST + kt * 32 + lc * 16;
                ldsm_x4(kfh[j], khT + koff);
                ldsm_x4(kfl[j], klT + koff);
            }
            #pragma unroll
            for (int mt = 0; mt < 2; mt++)
                #pragma unroll
                for (int j = 0; j < 4; j++) {
                    mma16816h(accs[mt * 8 + 2 * j],     ah[mt], kfh[j][0], kfh[j][2]);
                    mma16816h(accs[mt * 8 + 2 * j + 1], ah[mt], kfh[j][1], kfh[j][3]);
                }
            #pragma unroll
            for (int mt = 0; mt < 2; mt++)
                #pragma unroll
                for (int j = 0; j < 4; j++) {
                    mma16816h(accs[mt * 8 + 2 * j],     ah[mt], kfl[j][0], kfl[j][2]);
                    mma16816h(accs[mt * 8 + 2 * j + 1], ah[mt], kfl[j][1], kfl[j][3]);
                }
            #pragma unroll
            for (int mt = 0; mt < 2; mt++)
                #pragma unroll
                for (int j = 0; j < 4; j++) {
                    mma16816h(accs[mt * 8 + 2 * j],     al[mt], kfh[j][0], kfh[j][2]);
                    mma16816h(accs[mt * 8 + 2 * j + 1], al[mt], kfh[j][1], kfh[j][3]);
                }
        }

        #pragma unroll
        for (int mt = 0; mt < 2; mt++) {
            float mx0 = -1e30f, mx1 = -1e30f;
            #pragma unroll
            for (int nt = 0; nt < 8; nt++) {
                mx0 = fmaxf(mx0, fmaxf(accs[mt * 8 + nt][0], accs[mt * 8 + nt][1]));
                mx1 = fmaxf(mx1, fmaxf(accs[mt * 8 + nt][2], accs[mt * 8 + nt][3]));
            }
            mx0 = fmaxf(mx0, __shfl_xor_sync(0xffffffffu, mx0, 1));
            mx0 = fmaxf(mx0, __shfl_xor_sync(0xffffffffu, mx0, 2));
            mx1 = fmaxf(mx1, __shfl_xor_sync(0xffffffffu, mx1, 1));
            mx1 = fmaxf(mx1, __shfl_xor_sync(0xffffffffu, mx1, 2));
            float mn0 = fmaxf(mrow[mt * 2],     mx0);
            float mn1 = fmaxf(mrow[mt * 2 + 1], mx1);
            float al0 = ex2f(mrow[mt * 2]     - mn0);
            float al1 = ex2f(mrow[mt * 2 + 1] - mn1);
            mrow[mt * 2] = mn0; mrow[mt * 2 + 1] = mn1;
            float s0 = 0.f, s1 = 0.f;
            #pragma unroll
            for (int nt = 0; nt < 8; nt++) {
                float* a = accs[mt * 8 + nt];
                a[0] = ex2f(a[0] - mn0);
                a[1] = ex2f(a[1] - mn0);
                a[2] = ex2f(a[2] - mn1);
                a[3] = ex2f(a[3] - mn1);
                s0 += a[0] + a[1];
                s1 += a[2] + a[3];
            }
            s0 += __shfl_xor_sync(0xffffffffu, s0, 1);
            s0 += __shfl_xor_sync(0xffffffffu, s0, 2);
            s1 += __shfl_xor_sync(0xffffffffu, s1, 1);
            s1 += __shfl_xor_sync(0xffffffffu, s1, 2);
            lrow[mt * 2]     = lrow[mt * 2]     * al0 + s0;
            lrow[mt * 2 + 1] = lrow[mt * 2 + 1] * al1 + s1;
            #pragma unroll
            for (int nt = 0; nt < 8; nt++) {
                acco[mt * 8 + nt][0] *= al0; acco[mt * 8 + nt][1] *= al0;
                acco[mt * 8 + nt][2] *= al1; acco[mt * 8 + nt][3] *= al1;
            }
        }

        #pragma unroll
        for (int kt = 0; kt < 4; kt++) {
            uint32_t vbh[4][4], vbl[4][4];
            #pragma unroll
            for (int cg = 0; cg < 4; cg++) {
                uint32_t voff = (kt * 16 + lr) * AST + cg * 32 + lc * 16;
                ldsm_x4t(vbh[cg], vhT + voff);
                ldsm_x4t(vbl[cg], vlT + voff);
            }
            uint32_t ph[2][4], pl[2][4];
            #pragma unroll
            for (int mt = 0; mt < 2; mt++) {
                float* s0 = accs[mt * 8 + 2 * kt];
                float* s1 = accs[mt * 8 + 2 * kt + 1];
                ph[mt][0] = pk2h(s0[0], s0[1]);
                ph[mt][1] = pk2h(s0[2], s0[3]);
                ph[mt][2] = pk2h(s1[0], s1[1]);
                ph[mt][3] = pk2h(s1[2], s1[3]);
                float2 f0 = upk2h(ph[mt][0]), f1 = upk2h(ph[mt][1]);
                float2 f2 = upk2h(ph[mt][2]), f3 = upk2h(ph[mt][3]);
                pl[mt][0] = pk2h(s0[0] - f0.x, s0[1] - f0.y);
                pl[mt][1] = pk2h(s0[2] - f1.x, s0[3] - f1.y);
                pl[mt][2] = pk2h(s1[0] - f2.x, s1[1] - f2.y);
                pl[mt][3] = pk2h(s1[2] - f3.x, s1[3] - f3.y);
            }
            #pragma unroll
            for (int mt = 0; mt < 2; mt++)
                #pragma unroll
                for (int nt = 0; nt < 8; nt++)
                    mma16816h(acco[mt * 8 + nt], ph[mt],
                              vbh[nt >> 1][(nt & 1) * 2],
                              vbh[nt >> 1][(nt & 1) * 2 + 1]);
            #pragma unroll
            for (int mt = 0; mt < 2; mt++)
                #pragma unroll
                for (int nt = 0; nt < 8; nt++)
                    mma16816h(acco[mt * 8 + nt], pl[mt],
                              vbh[nt >> 1][(nt & 1) * 2],
                              vbh[nt >> 1][(nt & 1) * 2 + 1]);
            #pragma unroll
            for (int mt = 0; mt < 2; mt++)
                #pragma unroll
                for (int nt = 0; nt < 8; nt++)
                    mma16816h(acco[mt * 8 + nt], ph[mt],
                              vbl[nt >> 1][(nt & 1) * 2],
                              vbl[nt >> 1][(nt & 1) * 2 + 1]);
        }
        __syncthreads();
    }

    // epilogue: O/l -> fp16 (single; out-proj is 1-term)
    #pragma unroll
    for (int mt = 0; mt < 2; mt++) {
        float inv0 = 1.f / lrow[mt * 2];
        float inv1 = 1.f / lrow[mt * 2 + 1];
        size_t r0 = (qrow0 + wid * 32 + mt * 16 + g) * D_MODEL + hcol;
        size_t r1 = r0 + 8 * D_MODEL;
        #pragma unroll
        for (int nt = 0; nt < 8; nt++) {
            int col = nt * 8 + tg * 2;
            *(uint32_t*)&Oh[r0 + col] =
                pk2h(acco[mt * 8 + nt][0] * inv0, acco[mt * 8 + nt][1] * inv0);
            *(uint32_t*)&Oh[r1 + col] =
                pk2h(acco[mt * 8 + nt][2] * inv1, acco[mt * 8 + nt][3] * inv1);
        }
    }
}

// ============================================================
extern "C" void kernel_launch(void* const* d_in, const int* in_sizes, int n_in,
                              void* d_out, int out_size)
{
    const float* x = (const float*)d_in[0];
    float* out = (float*)d_out;

    hf *xh, *xl, *qh, *ql, *kh, *kl, *vh, *vl, *oh, *bh, *bl;
    cudaGetSymbolAddress((void**)&xh, g_xh);
    cudaGetSymbolAddress((void**)&xl, g_xl);
    cudaGetSymbolAddress((void**)&qh, g_Qh);
    cudaGetSymbolAddress((void**)&ql, g_Ql);
    cudaGetSymbolAddress((void**)&kh, g_Kh);
    cudaGetSymbolAddress((void**)&kl, g_Kl);
    cudaGetSymbolAddress((void**)&vh, g_Vh);
    cudaGetSymbolAddress((void**)&vl, g_Vl);
    cudaGetSymbolAddress((void**)&oh, g_Oh);
    cudaGetSymbolAddress((void**)&bh, g_Wh);
    cudaGetSymbolAddress((void**)&bl, g_Wl);
    const size_t WSTR = (size_t)D_MODEL * D_MODEL;

    static int cfg_done = 0;
    if (!cfg_done) {
        cudaFuncSetAttribute(hgemm12<0>,
            cudaFuncAttributeMaxDynamicSharedMemorySize, GEM_SMEM);
        cudaFuncSetAttribute(hgemm12<1>,
            cudaFuncAttributeMaxDynamicSharedMemorySize, GEM_SMEM);
        cudaFuncSetAttribute(attn_mma5,
            cudaFuncAttributeMaxDynamicSharedMemorySize, ATT_SMEM);
        cfg_done = 1;
    }

    // splits: x, then all 4 weights in one launch
    fsplit<<<MROWS * D_MODEL / 1024, 256>>>(x, xh, xl);
    wsplit4<<<dim3(D_MODEL * D_MODEL / 1024, 1, 4), 256>>>(
        (const float*)d_in[1], (const float*)d_in[2],
        (const float*)d_in[3], (const float*)d_in[4], bh, bl);

    // QKV projections fused (z=0,1: 3-term; z=2 (V): single-pass)
    hgemm12<1><<<dim3(D_MODEL / 64, MROWS / 128, 3), 128, GEM_SMEM>>>(
        xh, xl, bh, bl, nullptr, qh, ql, kh, kl, vh, vl);

    attn_mma5<<<dim3(SEQ / 128, HEADS, BATCH), 128, ATT_SMEM>>>(
        qh, ql, kh, kl, vh, vl, oh);

    // final projection: single-pass fp16 (lo pointers unused)
    hgemm12<0><<<dim3(D_MODEL / 64, MROWS / 128, 1), 128, GEM_SMEM>>>(
        oh, oh, bh + 3 * WSTR, bl + 3 * WSTR, out,
        nullptr, nullptr, nullptr, nullptr, nullptr, nullptr);
}

// round 17
// speedup vs baseline: 1.3470x; 1.0619x over previous
#include <cuda_runtime.h>
#include <cuda_fp16.h>
#include <math.h>
#include <cstdint>

#define D_MODEL 1024
#define HEADS   16
#define DH      64
#define SEQ     1024
#define BATCH   8
#define MROWS   (BATCH*SEQ)   // 8192

typedef __half hf;

// ---- scratch (no cudaMalloc allowed) ----
__device__ hf g_xh[MROWS*D_MODEL];
__device__ hf g_xl[MROWS*D_MODEL];
__device__ hf g_Qh[MROWS*D_MODEL];
__device__ hf g_Ql[MROWS*D_MODEL];
__device__ hf g_Kh[MROWS*D_MODEL];
__device__ hf g_Kl[MROWS*D_MODEL];
__device__ hf g_Vh[MROWS*D_MODEL];
__device__ hf g_Oh[MROWS*D_MODEL];
__device__ hf g_Wh[4][D_MODEL*D_MODEL];  // natural [k][n]
__device__ hf g_Wl[4][D_MODEL*D_MODEL];

#define QSC (0.125f * 1.44269504088896f)   // 1/sqrt(dh) * log2(e)

// ============================================================
// PTX helpers (sm_80-era only; tcgen05 unavailable at .target sm_103)
// ============================================================
__device__ __forceinline__ uint32_t smem_u32(const void* p) {
    uint32_t a;
    asm("{ .reg .u64 t; cvta.to.shared.u64 t, %1; cvt.u32.u64 %0, t; }"
        : "=r"(a) : "l"(p));
    return a;
}
__device__ __forceinline__ void cpa16(uint32_t dst, const void* src) {
    asm volatile("cp.async.cg.shared.global [%0], [%1], 16;"
                 :: "r"(dst), "l"(src) : "memory");
}
#define CP_COMMIT() asm volatile("cp.async.commit_group;" ::: "memory")
#define CP_WAIT1()  asm volatile("cp.async.wait_group 1;" ::: "memory")
#define CP_WAIT0()  asm volatile("cp.async.wait_group 0;" ::: "memory")

__device__ __forceinline__ void ldsm_x4(uint32_t* r, uint32_t addr) {
    asm volatile("ldmatrix.sync.aligned.m8n8.x4.shared.b16 {%0,%1,%2,%3}, [%4];"
                 : "=r"(r[0]), "=r"(r[1]), "=r"(r[2]), "=r"(r[3]) : "r"(addr));
}
__device__ __forceinline__ void ldsm_x4t(uint32_t* r, uint32_t addr) {
    asm volatile("ldmatrix.sync.aligned.m8n8.x4.trans.shared.b16 {%0,%1,%2,%3}, [%4];"
                 : "=r"(r[0]), "=r"(r[1]), "=r"(r[2]), "=r"(r[3]) : "r"(addr));
}
// fp16 mma, fp32 accumulate
__device__ __forceinline__ void mma16816h(float* c, const uint32_t* a,
                                          uint32_t b0, uint32_t b1) {
    asm volatile(
        "mma.sync.aligned.m16n8k16.row.col.f32.f16.f16.f32 "
        "{%0,%1,%2,%3}, {%4,%5,%6,%7}, {%8,%9}, {%0,%1,%2,%3};"
        : "+f"(c[0]), "+f"(c[1]), "+f"(c[2]), "+f"(c[3])
        : "r"(a[0]), "r"(a[1]), "r"(a[2]), "r"(a[3]), "r"(b0), "r"(b1));
}
__device__ __forceinline__ float ex2f(float x) {
    float r; asm("ex2.approx.f32 %0, %1;" : "=f"(r) : "f"(x)); return r;
}
__device__ __forceinline__ uint32_t pk2h(float lo, float hi) {   // f16x2 {lo,hi}
    __half2 t = __floats2half2_rn(lo, hi);
    return *reinterpret_cast<uint32_t*>(&t);
}
__device__ __forceinline__ float2 upk2h(uint32_t v) {
    __half2 t = *reinterpret_cast<__half2*>(&v);
    return __half22float2(t);
}

// ============================================================
// splits: fp32 -> fp16 hi/lo
// ============================================================
__device__ __forceinline__ void split4(const float* __restrict__ X,
                                       hf* __restrict__ Xh,
                                       hf* __restrict__ Xl, size_t i) {
    float4 v = *(const float4*)&X[i];
    float a[4] = {v.x, v.y, v.z, v.w};
    hf h[4], l[4];
    #pragma unroll
    for (int j = 0; j < 4; j++) {
        h[j] = __float2half_rn(a[j]);
        l[j] = __float2half_rn(a[j] - __half2float(h[j]));
    }
    *(__half2*)&Xh[i]     = __halves2half2(h[0], h[1]);
    *(__half2*)&Xh[i + 2] = __halves2half2(h[2], h[3]);
    *(__half2*)&Xl[i]     = __halves2half2(l[0], l[1]);
    *(__half2*)&Xl[i + 2] = __halves2half2(l[2], l[3]);
}
__global__ void fsplit(const float* __restrict__ X,
                       hf* __restrict__ Xh, hf* __restrict__ Xl) {
    size_t i = (size_t)(blockIdx.x * blockDim.x + threadIdx.x) * 4;
    split4(X, Xh, Xl, i);
}
__global__ void wsplit4(const float* __restrict__ w0, const float* __restrict__ w1,
                        const float* __restrict__ w2, const float* __restrict__ w3,
                        hf* __restrict__ Wh, hf* __restrict__ Wl) {
    int z = blockIdx.z;
    const float* W = (z == 0) ? w0 : (z == 1) ? w1 : (z == 2) ? w2 : w3;
    size_t off = (size_t)z * D_MODEL * D_MODEL;
    size_t i = (size_t)(blockIdx.x * blockDim.x + threadIdx.x) * 4;
    split4(W, Wh + off, Wl + off, i);
}

// ============================================================
// hgemm13: C[M,1024] = A @ W via fp16 split on mma.sync.
//   CTA 128x64, 128 threads = 4 warps of 32x64, 3 CTAs/SM,
//   BK=32 double-buffered (R15/R16-proven shape).
//   Q/K (z=0,1): 3-term split, hi+lo outputs.
//   V (z=2): single-pass, HI-ONLY output (Vl dropped: PV keeps
//   Pl*Vh only; V already carries ~4e-4 from its 1-pass GEMM).
//   Out-proj (MODE 0): single-pass, fp32 out.
// ============================================================
#define AST9 80                          // A smem row stride (40 hf)
#define BST11 144                        // B smem row stride (72 hf)
#define ABYT11 (128 * AST9)              // 10240
#define BBYT11 (32 * BST11)              // 4608
#define STG11 (2 * ABYT11 + 2 * BBYT11)  // 29696
#define NST11 32                         // K chunks of 32
#define GEM_SMEM (2 * STG11)             // 59392 -> 3 CTAs/SM

__device__ __forceinline__ void gload13(uint32_t st,
    const hf* __restrict__ Ah, const hf* __restrict__ Al,
    const hf* __restrict__ Bh, const hf* __restrict__ Bl,
    int m0, int n0, int kk0, int tid, bool lo)
{
    #pragma unroll
    for (int t = 0; t < 4; t++) {            // A: 128x32 (512 chunks)
        int idx = tid + (t << 7);
        int r = idx >> 2, c = idx & 3;
        size_t go = (size_t)(m0 + r) * D_MODEL + kk0 + c * 8;
        uint32_t so = st + r * AST9 + c * 16;
        cpa16(so, Ah + go);
        if (lo) cpa16(so + ABYT11, Al + go);
    }
    #pragma unroll
    for (int t = 0; t < 2; t++) {            // B: 32x64 (256 chunks)
        int idx = tid + (t << 7);
        int r = idx >> 3, c = idx & 7;
        size_t go = (size_t)(kk0 + r) * D_MODEL + n0 + c * 8;
        uint32_t so = st + 2 * ABYT11 + r * BST11 + c * 16;
        cpa16(so, Bh + go);
        if (lo) cpa16(so + BBYT11, Bl + go);
    }
}

// fused 3-term pass over one BK=32 chunk, term-outer, 32x64 warp tile
__device__ __forceinline__ void gpass3(float acc[16][4],
    uint32_t aH, uint32_t aL, uint32_t bH, uint32_t bL,
    int wid, int lr, int lc)
{
    #pragma unroll
    for (int k16 = 0; k16 < 2; k16++) {
        uint32_t ah[2][4], al[2][4];
        #pragma unroll
        for (int mt = 0; mt < 2; mt++) {
            uint32_t aoff = (wid * 32 + mt * 16 + lr) * AST9 + k16 * 32 + lc * 16;
            ldsm_x4(ah[mt], aH + aoff);
            ldsm_x4(al[mt], aL + aoff);
        }
        #pragma unroll
        for (int cg = 0; cg < 4; cg++) {
            uint32_t boff = (k16 * 16 + lr) * BST11 + cg * 32 + lc * 16;
            uint32_t bh4[4], bl4[4];
            ldsm_x4t(bh4, bH + boff);
            ldsm_x4t(bl4, bL + boff);
            #pragma unroll
            for (int half = 0; half < 2; half++)
                #pragma unroll
                for (int mt = 0; mt < 2; mt++)
                    mma16816h(acc[mt * 8 + cg * 2 + half], ah[mt],
                              bh4[half * 2], bh4[half * 2 + 1]);
            #pragma unroll
            for (int half = 0; half < 2; half++)
                #pragma unroll
                for (int mt = 0; mt < 2; mt++)
                    mma16816h(acc[mt * 8 + cg * 2 + half], ah[mt],
                              bl4[half * 2], bl4[half * 2 + 1]);
            #pragma unroll
            for (int half = 0; half < 2; half++)
                #pragma unroll
                for (int mt = 0; mt < 2; mt++)
                    mma16816h(acc[mt * 8 + cg * 2 + half], al[mt],
                              bh4[half * 2], bh4[half * 2 + 1]);
        }
    }
}

// single-term pass (hi*hi only)
__device__ __forceinline__ void gpass1(float acc[16][4],
    uint32_t aH, uint32_t bH, int wid, int lr, int lc)
{
    #pragma unroll
    for (int k16 = 0; k16 < 2; k16++) {
        uint32_t ah[2][4];
        #pragma unroll
        for (int mt = 0; mt < 2; mt++) {
            uint32_t aoff = (wid * 32 + mt * 16 + lr) * AST9 + k16 * 32 + lc * 16;
            ldsm_x4(ah[mt], aH + aoff);
        }
        #pragma unroll
        for (int cg = 0; cg < 4; cg++) {
            uint32_t boff = (k16 * 16 + lr) * BST11 + cg * 32 + lc * 16;
            uint32_t bh4[4];
            ldsm_x4t(bh4, bH + boff);
            #pragma unroll
            for (int half = 0; half < 2; half++)
                #pragma unroll
                for (int mt = 0; mt < 2; mt++)
                    mma16816h(acc[mt * 8 + cg * 2 + half], ah[mt],
                              bh4[half * 2], bh4[half * 2 + 1]);
        }
    }
}

template<int MODE>
__global__ __launch_bounds__(128, 3) void hgemm13(
    const hf* __restrict__ Ah, const hf* __restrict__ Al,
    const hf* __restrict__ BhB, const hf* __restrict__ BlB,
    float* __restrict__ C,
    hf* __restrict__ Ch0, hf* __restrict__ Cl0,
    hf* __restrict__ Ch1, hf* __restrict__ Cl1,
    hf* __restrict__ Ch2)
{
    extern __shared__ char dsm[];
    const uint32_t sb = smem_u32(dsm);

    const int tid = threadIdx.x;
    const int wid = tid >> 5;
    const int lane = tid & 31;
    const int lr = lane & 15, lc = lane >> 4;
    const int m0 = blockIdx.y << 7;
    const int n0 = blockIdx.x << 6;
    const int z  = blockIdx.z;
    const bool three = (MODE == 1) && (z != 2);   // V and out-proj: 1-term

    const hf* Bh = BhB + (size_t)z * D_MODEL * D_MODEL;
    const hf* Bl = BlB + (size_t)z * D_MODEL * D_MODEL;

    float acc[16][4];
    #pragma unroll
    for (int i = 0; i < 16; i++)
        #pragma unroll
        for (int j = 0; j < 4; j++) acc[i][j] = 0.f;

    gload13(sb, Ah, Al, Bh, Bl, m0, n0, 0, tid, three);
    CP_COMMIT();

    #pragma unroll 1
    for (int s = 0; s < NST11; s++) {
        if (s + 1 < NST11) {
            gload13(sb + ((s + 1) & 1) * STG11, Ah, Al, Bh, Bl,
                    m0, n0, (s + 1) << 5, tid, three);
            CP_COMMIT();
            CP_WAIT1();
        } else {
            CP_WAIT0();
        }
        __syncthreads();

        const uint32_t base = sb + (s & 1) * STG11;
        if (three)
            gpass3(acc, base, base + ABYT11,
                   base + 2 * ABYT11, base + 2 * ABYT11 + BBYT11,
                   wid, lr, lc);
        else
            gpass1(acc, base, base + 2 * ABYT11, wid, lr, lc);
        __syncthreads();
    }

    const int g = lane >> 2, tg = lane & 3;
    const float scale = (MODE == 1 && z == 0) ? QSC : 1.0f;
    hf* Ch = (z == 0) ? Ch0 : (z == 1) ? Ch1 : Ch2;
    hf* Cl = (z == 0) ? Cl0 : (z == 1) ? Cl1 : nullptr;   // V: hi only

    #pragma unroll
    for (int mt = 0; mt < 2; mt++) {
        int row = m0 + wid * 32 + mt * 16 + g;
        #pragma unroll
        for (int nt = 0; nt < 8; nt++) {
            int col = n0 + nt * 8 + tg * 2;
            float* ac = acc[mt * 8 + nt];
            if (MODE == 0) {
                float* cp = &C[(size_t)row * D_MODEL + col];
                *(float2*)cp = make_float2(ac[0], ac[1]);
                *(float2*)(cp + 8 * D_MODEL) = make_float2(ac[2], ac[3]);
            } else {
                float v0 = ac[0] * scale, v1 = ac[1] * scale;
                float v2 = ac[2] * scale, v3 = ac[3] * scale;
                uint32_t h01 = pk2h(v0, v1), h23 = pk2h(v2, v3);
                size_t o0 = (size_t)row * D_MODEL + col;
                size_t o1 = o0 + 8 * D_MODEL;
                *(uint32_t*)&Ch[o0] = h01;
                *(uint32_t*)&Ch[o1] = h23;
                if (Cl) {
                    float2 f01 = upk2h(h01), f23 = upk2h(h23);
                    *(uint32_t*)&Cl[o0] = pk2h(v0 - f01.x, v1 - f01.y);
                    *(uint32_t*)&Cl[o1] = pk2h(v2 - f23.x, v3 - f23.y);
                }
            }
        }
    }
}

// ============================================================
// attn_mma6: R16 attention with PV reduced to 2 terms
// (Ph*Vh + Pl*Vh; Vl eliminated entirely). KV stage = 3 tiles.
// 128 queries/CTA, 4 warps x 32 q-rows, 2 CTAs/SM.
// ============================================================
#define AST 144
#define QTB4  (128 * AST)                // 18432
#define KVB   (64 * AST)                 // 9216
#define KVST3 (3 * KVB)                  // Kh,Kl,Vh per stage = 27648
#define KVOFF4 (2 * QTB4)                // 36864
#define ATT_SMEM (KVOFF4 + 2 * KVST3)    // 92160 -> 2 CTAs/SM

__device__ __forceinline__ void kvload3(uint32_t st,
    const hf* __restrict__ Kh, const hf* __restrict__ Kl,
    const hf* __restrict__ Vh, size_t gbase, int tid)
{
    #pragma unroll
    for (int t = 0; t < 4; t++) {
        int idx = tid + (t << 7);
        int r = idx >> 3, c = idx & 7;
        size_t go = gbase + (size_t)r * D_MODEL + c * 8;
        uint32_t so = st + r * AST + c * 16;
        cpa16(so,           Kh + go);
        cpa16(so + KVB,     Kl + go);
        cpa16(so + 2 * KVB, Vh + go);
    }
}

__global__ __launch_bounds__(128, 2) void attn_mma6(
    const hf* __restrict__ Qh, const hf* __restrict__ Ql,
    const hf* __restrict__ Kh, const hf* __restrict__ Kl,
    const hf* __restrict__ Vh, hf* __restrict__ Oh)
{
    extern __shared__ char dsm[];
    const uint32_t sb = smem_u32(dsm);

    const int tid = threadIdx.x;
    const int wid = tid >> 5;
    const int lane = tid & 31;
    const int lr = lane & 15, lc = lane >> 4;
    const int g = lane >> 2, tg = lane & 3;
    const int qb = blockIdx.x, h = blockIdx.y, b = blockIdx.z;
    const size_t qrow0 = (size_t)(b * SEQ + qb * 128);
    const size_t hcol = h * DH;

    #pragma unroll
    for (int t = 0; t < 8; t++) {
        int idx = tid + (t << 7);
        int r = idx >> 3, c = idx & 7;
        size_t go = (qrow0 + r) * D_MODEL + hcol + c * 8;
        uint32_t so = sb + r * AST + c * 16;
        cpa16(so, Qh + go);
        cpa16(so + QTB4, Ql + go);
    }
    CP_COMMIT();

    kvload3(sb + KVOFF4, Kh, Kl, Vh, (size_t)(b * SEQ) * D_MODEL + hcol, tid);
    CP_COMMIT();

    float acco[16][4];
    #pragma unroll
    for (int i = 0; i < 16; i++)
        #pragma unroll
        for (int j = 0; j < 4; j++) acco[i][j] = 0.f;
    float mrow[4] = {-1e30f, -1e30f, -1e30f, -1e30f};
    float lrow[4] = {0.f, 0.f, 0.f, 0.f};

    #pragma unroll 1
    for (int kb = 0; kb < 16; kb++) {
        if (kb < 15)
            kvload3(sb + KVOFF4 + ((kb + 1) & 1) * KVST3, Kh, Kl, Vh,
                    (size_t)(b * SEQ + (kb + 1) * 64) * D_MODEL + hcol, tid);
        CP_COMMIT();
        CP_WAIT1();
        __syncthreads();

        const uint32_t kst = sb + KVOFF4 + (kb & 1) * KVST3;
        const uint32_t khT = kst, klT = kst + KVB;
        const uint32_t vhT = kst + 2 * KVB;

        float accs[16][4];
        #pragma unroll
        for (int i = 0; i < 16; i++)
            #pragma unroll
            for (int j = 0; j < 4; j++) accs[i][j] = 0.f;

        #pragma unroll
        for (int kt = 0; kt < 4; kt++) {
            uint32_t ah[2][4], al[2][4], kfh[4][4], kfl[4][4];
            #pragma unroll
            for (int mt = 0; mt < 2; mt++) {
                uint32_t qoff = (wid * 32 + mt * 16 + lr) * AST + kt * 32 + lc * 16;
                ldsm_x4(ah[mt], sb + qoff);
                ldsm_x4(al[mt], sb + QTB4 + qoff);
            }
            #pragma unroll
            for (int j = 0; j < 4; j++) {
                uint32_t koff = (j * 16 + lr) * AST + kt * 32 + lc * 16;
                ldsm_x4(kfh[j], khT + koff);
                ldsm_x4(kfl[j], klT + koff);
            }
            #pragma unroll
            for (int mt = 0; mt < 2; mt++)
                #pragma unroll
                for (int j = 0; j < 4; j++) {
                    mma16816h(accs[mt * 8 + 2 * j],     ah[mt], kfh[j][0], kfh[j][2]);
                    mma16816h(accs[mt * 8 + 2 * j + 1], ah[mt], kfh[j][1], kfh[j][3]);
                }
            #pragma unroll
            for (int mt = 0; mt < 2; mt++)
                #pragma unroll
                for (int j = 0; j < 4; j++) {
                    mma16816h(accs[mt * 8 + 2 * j],     ah[mt], kfl[j][0], kfl[j][2]);
                    mma16816h(accs[mt * 8 + 2 * j + 1], ah[mt], kfl[j][1], kfl[j][3]);
                }
            #pragma unroll
            for (int mt = 0; mt < 2; mt++)
                #pragma unroll
                for (int j = 0; j < 4; j++) {
                    mma16816h(accs[mt * 8 + 2 * j],     al[mt], kfh[j][0], kfh[j][2]);
                    mma16816h(accs[mt * 8 + 2 * j + 1], al[mt], kfh[j][1], kfh[j][3]);
                }
        }

        #pragma unroll
        for (int mt = 0; mt < 2; mt++) {
            float mx0 = -1e30f, mx1 = -1e30f;
            #pragma unroll
            for (int nt = 0; nt < 8; nt++) {
                mx0 = fmaxf(mx0, fmaxf(accs[mt * 8 + nt][0], accs[mt * 8 + nt][1]));
                mx1 = fmaxf(mx1, fmaxf(accs[mt * 8 + nt][2], accs[mt * 8 + nt][3]));
            }
            mx0 = fmaxf(mx0, __shfl_xor_sync(0xffffffffu, mx0, 1));
            mx0 = fmaxf(mx0, __shfl_xor_sync(0xffffffffu, mx0, 2));
            mx1 = fmaxf(mx1, __shfl_xor_sync(0xffffffffu, mx1, 1));
            mx1 = fmaxf(mx1, __shfl_xor_sync(0xffffffffu, mx1, 2));
            float mn0 = fmaxf(mrow[mt * 2],     mx0);
            float mn1 = fmaxf(mrow[mt * 2 + 1], mx1);
            float al0 = ex2f(mrow[mt * 2]     - mn0);
            float al1 = ex2f(mrow[mt * 2 + 1] - mn1);
            mrow[mt * 2] = mn0; mrow[mt * 2 + 1] = mn1;
            float s0 = 0.f, s1 = 0.f;
            #pragma unroll
            for (int nt = 0; nt < 8; nt++) {
                float* a = accs[mt * 8 + nt];
                a[0] = ex2f(a[0] - mn0);
                a[1] = ex2f(a[1] - mn0);
                a[2] = ex2f(a[2] - mn1);
                a[3] = ex2f(a[3] - mn1);
                s0 += a[0] + a[1];
                s1 += a[2] + a[3];
            }
            s0 += __shfl_xor_sync(0xffffffffu, s0, 1);
            s0 += __shfl_xor_sync(0xffffffffu, s0, 2);
            s1 += __shfl_xor_sync(0xffffffffu, s1, 1);
            s1 += __shfl_xor_sync(0xffffffffu, s1, 2);
            lrow[mt * 2]     = lrow[mt * 2]     * al0 + s0;
            lrow[mt * 2 + 1] = lrow[mt * 2 + 1] * al1 + s1;
            #pragma unroll
            for (int nt = 0; nt < 8; nt++) {
                acco[mt * 8 + nt][0] *= al0; acco[mt * 8 + nt][1] *= al0;
                acco[mt * 8 + nt][2] *= al1; acco[mt * 8 + nt][3] *= al1;
            }
        }

        // ---- O += P V, 2 terms (Ph*Vh + Pl*Vh), term-outer ----
        #pragma unroll
        for (int kt = 0; kt < 4; kt++) {
            uint32_t vbh[4][4];
            #pragma unroll
            for (int cg = 0; cg < 4; cg++) {
                uint32_t voff = (kt * 16 + lr) * AST + cg * 32 + lc * 16;
                ldsm_x4t(vbh[cg], vhT + voff);
            }
            uint32_t ph[2][4], pl[2][4];
            #pragma unroll
            for (int mt = 0; mt < 2; mt++) {
                float* s0 = accs[mt * 8 + 2 * kt];
                float* s1 = accs[mt * 8 + 2 * kt + 1];
                ph[mt][0] = pk2h(s0[0], s0[1]);
                ph[mt][1] = pk2h(s0[2], s0[3]);
                ph[mt][2] = pk2h(s1[0], s1[1]);
                ph[mt][3] = pk2h(s1[2], s1[3]);
                float2 f0 = upk2h(ph[mt][0]), f1 = upk2h(ph[mt][1]);
                float2 f2 = upk2h(ph[mt][2]), f3 = upk2h(ph[mt][3]);
                pl[mt][0] = pk2h(s0[0] - f0.x, s0[1] - f0.y);
                pl[mt][1] = pk2h(s0[2] - f1.x, s0[3] - f1.y);
                pl[mt][2] = pk2h(s1[0] - f2.x, s1[1] - f2.y);
                pl[mt][3] = pk2h(s1[2] - f3.x, s1[3] - f3.y);
            }
            #pragma unroll
            for (int mt = 0; mt < 2; mt++)
                #pragma unroll
                for (int nt = 0; nt < 8; nt++)
                    mma16816h(acco[mt * 8 + nt], ph[mt],
                              vbh[nt >> 1][(nt & 1) * 2],
                              vbh[nt >> 1][(nt & 1) * 2 + 1]);
            #pragma unroll
            for (int mt = 0; mt < 2; mt++)
                #pragma unroll
                for (int nt = 0; nt < 8; nt++)
                    mma16816h(acco[mt * 8 + nt], pl[mt],
                              vbh[nt >> 1][(nt & 1) * 2],
                              vbh[nt >> 1][(nt & 1) * 2 + 1]);
        }
        __syncthreads();
    }

    // epilogue: O/l -> fp16 (single; out-proj is 1-term)
    #pragma unroll
    for (int mt = 0; mt < 2; mt++) {
        float inv0 = 1.f / lrow[mt * 2];
        float inv1 = 1.f / lrow[mt * 2 + 1];
        size_t r0 = (qrow0 + wid * 32 + mt * 16 + g) * D_MODEL + hcol;
        size_t r1 = r0 + 8 * D_MODEL;
        #pragma unroll
        for (int nt = 0; nt < 8; nt++) {
            int col = nt * 8 + tg * 2;
            *(uint32_t*)&Oh[r0 + col] =
                pk2h(acco[mt * 8 + nt][0] * inv0, acco[mt * 8 + nt][1] * inv0);
            *(uint32_t*)&Oh[r1 + col] =
                pk2h(acco[mt * 8 + nt][2] * inv1, acco[mt * 8 + nt][3] * inv1);
        }
    }
}

// ============================================================
extern "C" void kernel_launch(void* const* d_in, const int* in_sizes, int n_in,
                              void* d_out, int out_size)
{
    const float* x = (const float*)d_in[0];
    float* out = (float*)d_out;

    hf *xh, *xl, *qh, *ql, *kh, *kl, *vh, *oh, *bh, *bl;
    cudaGetSymbolAddress((void**)&xh, g_xh);
    cudaGetSymbolAddress((void**)&xl, g_xl);
    cudaGetSymbolAddress((void**)&qh, g_Qh);
    cudaGetSymbolAddress((void**)&ql, g_Ql);
    cudaGetSymbolAddress((void**)&kh, g_Kh);
    cudaGetSymbolAddress((void**)&kl, g_Kl);
    cudaGetSymbolAddress((void**)&vh, g_Vh);
    cudaGetSymbolAddress((void**)&oh, g_Oh);
    cudaGetSymbolAddress((void**)&bh, g_Wh);
    cudaGetSymbolAddress((void**)&bl, g_Wl);
    const size_t WSTR = (size_t)D_MODEL * D_MODEL;

    static int cfg_done = 0;
    if (!cfg_done) {
        cudaFuncSetAttribute(hgemm13<0>,
            cudaFuncAttributeMaxDynamicSharedMemorySize, GEM_SMEM);
        cudaFuncSetAttribute(hgemm13<1>,
            cudaFuncAttributeMaxDynamicSharedMemorySize, GEM_SMEM);
        cudaFuncSetAttribute(attn_mma6,
            cudaFuncAttributeMaxDynamicSharedMemorySize, ATT_SMEM);
        cfg_done = 1;
    }

    // splits: x, then all 4 weights in one launch
    fsplit<<<MROWS * D_MODEL / 1024, 256>>>(x, xh, xl);
    wsplit4<<<dim3(D_MODEL * D_MODEL / 1024, 1, 4), 256>>>(
        (const float*)d_in[1], (const float*)d_in[2],
        (const float*)d_in[3], (const float*)d_in[4], bh, bl);

    // QKV projections fused (z=0,1: 3-term hi+lo; z=2 V: 1-pass hi-only)
    hgemm13<1><<<dim3(D_MODEL / 64, MROWS / 128, 3), 128, GEM_SMEM>>>(
        xh, xl, bh, bl, nullptr, qh, ql, kh, kl, vh);

    attn_mma6<<<dim3(SEQ / 128, HEADS, BATCH), 128, ATT_SMEM>>>(
        qh, ql, kh, kl, vh, oh);

    // final projection: single-pass fp16 (lo path unused)
    hgemm13<0><<<dim3(D_MODEL / 64, MROWS / 128, 1), 128, GEM_SMEM>>>(
        oh, oh, bh + 3 * WSTR, bl + 3 * WSTR, out,
        nullptr, nullptr, nullptr, nullptr, nullptr);
}